// round 3
// baseline (speedup 1.0000x reference)
#include <cuda_runtime.h>
#include <math.h>

// ---------------- problem constants ----------------
#define CB   2
#define CN   2048
#define CHD  2048
#define CNH  16
#define CKVH 4
#define CD   128
#define CKVD 512
#define CM   (CB*CN)   // 4096 token rows

// ---------------- scratch (device globals; no allocation allowed) ----------------
__device__ float g_xn[CM*CHD];   // normalized tokens
__device__ float g_q [CM*CHD];   // Q
__device__ float g_k [CM*CKVD];  // K
__device__ float g_v [CM*CKVD];  // V
__device__ float g_a [CM*CHD];   // attention output (pre-Wo)

// ======================================================================
// RMSNorm: one block per row, 256 threads, float4 vectorized
// ======================================================================
__global__ __launch_bounds__(256)
void rmsnorm_kernel(const float* __restrict__ x, const float* __restrict__ w,
                    float* __restrict__ y)
{
    const int row = blockIdx.x;
    const int tid = threadIdx.x;
    const float4* xr = reinterpret_cast<const float4*>(x + (size_t)row * CHD);
    float4 v0 = xr[tid];
    float4 v1 = xr[tid + 256];
    float ss = v0.x*v0.x + v0.y*v0.y + v0.z*v0.z + v0.w*v0.w
             + v1.x*v1.x + v1.y*v1.y + v1.z*v1.z + v1.w*v1.w;
#pragma unroll
    for (int o = 16; o > 0; o >>= 1) ss += __shfl_xor_sync(0xffffffffu, ss, o);
    __shared__ float red[8];
    if ((tid & 31) == 0) red[tid >> 5] = ss;
    __syncthreads();
    float tot = red[0]+red[1]+red[2]+red[3]+red[4]+red[5]+red[6]+red[7];
    // eps = finfo(float32).eps
    const float sc = rsqrtf(tot * (1.0f / (float)CHD) + 1.1920929e-7f);
    const float4* wr = reinterpret_cast<const float4*>(w);
    float4* yr = reinterpret_cast<float4*>(y + (size_t)row * CHD);
    float4 w0 = wr[tid], w1 = wr[tid + 256];
    float4 o0, o1;
    o0.x = v0.x*sc*w0.x; o0.y = v0.y*sc*w0.y; o0.z = v0.z*sc*w0.z; o0.w = v0.w*sc*w0.w;
    o1.x = v1.x*sc*w1.x; o1.y = v1.y*sc*w1.y; o1.z = v1.z*sc*w1.z; o1.w = v1.w*sc*w1.w;
    yr[tid] = o0;
    yr[tid + 256] = o1;
}

// ======================================================================
// SGEMM NT: C[M,Nout] = A[M,K] @ B[Nout,K]^T + bias
// 128x128 block tile, BK=8, 256 threads, 8x8 microtile
// ======================================================================
#define GBM 128
#define GBN 128
#define GBK 8
#define GTM 8
#define GTN 8
#define GPAD 4

__global__ __launch_bounds__(256)
void sgemm_nt(int M, int Nout, int K,
              const float* __restrict__ A, const float* __restrict__ B,
              const float* __restrict__ bias, float* __restrict__ C)
{
    __shared__ float As[GBK][GBM + GPAD];
    __shared__ float Bs[GBK][GBN + GPAD];

    const int bn = blockIdx.x;
    const int bm = blockIdx.y;
    const int tid = threadIdx.x;
    const int tx = tid & 15;   // col group
    const int ty = tid >> 4;   // row group

    const int lr = tid >> 1;          // 0..127 : row within tile
    const int lc = (tid & 1) * 4;     // 0 or 4 : k offset

    const float* Ap = A + (size_t)(bm*GBM + lr) * K + lc;
    const float* Bp = B + (size_t)(bn*GBN + lr) * K + lc;

    float acc[GTM][GTN];
#pragma unroll
    for (int i = 0; i < GTM; i++)
#pragma unroll
        for (int j = 0; j < GTN; j++) acc[i][j] = 0.0f;

    for (int kt = 0; kt < K; kt += GBK) {
        float4 av = *reinterpret_cast<const float4*>(Ap + kt);
        float4 bv = *reinterpret_cast<const float4*>(Bp + kt);
        As[lc+0][lr] = av.x; As[lc+1][lr] = av.y; As[lc+2][lr] = av.z; As[lc+3][lr] = av.w;
        Bs[lc+0][lr] = bv.x; Bs[lc+1][lr] = bv.y; Bs[lc+2][lr] = bv.z; Bs[lc+3][lr] = bv.w;
        __syncthreads();
#pragma unroll
        for (int k = 0; k < GBK; k++) {
            float ar[GTM], br[GTN];
            *reinterpret_cast<float4*>(ar)     = *reinterpret_cast<const float4*>(&As[k][ty*GTM]);
            *reinterpret_cast<float4*>(ar + 4) = *reinterpret_cast<const float4*>(&As[k][ty*GTM + 4]);
            *reinterpret_cast<float4*>(br)     = *reinterpret_cast<const float4*>(&Bs[k][tx*GTN]);
            *reinterpret_cast<float4*>(br + 4) = *reinterpret_cast<const float4*>(&Bs[k][tx*GTN + 4]);
#pragma unroll
            for (int i = 0; i < GTM; i++)
#pragma unroll
                for (int j = 0; j < GTN; j++)
                    acc[i][j] += ar[i] * br[j];
        }
        __syncthreads();
    }

    // epilogue + bias
    float bvals[GTN];
#pragma unroll
    for (int j = 0; j < GTN; j++) bvals[j] = bias[bn*GBN + tx*GTN + j];
#pragma unroll
    for (int i = 0; i < GTM; i++) {
        const int row = bm*GBM + ty*GTM + i;
        float* Cp = C + (size_t)row * Nout + bn*GBN + tx*GTN;
        float4 o0, o1;
        o0.x = acc[i][0] + bvals[0]; o0.y = acc[i][1] + bvals[1];
        o0.z = acc[i][2] + bvals[2]; o0.w = acc[i][3] + bvals[3];
        o1.x = acc[i][4] + bvals[4]; o1.y = acc[i][5] + bvals[5];
        o1.z = acc[i][6] + bvals[6]; o1.w = acc[i][7] + bvals[7];
        *reinterpret_cast<float4*>(Cp)     = o0;
        *reinterpret_cast<float4*>(Cp + 4) = o1;
    }
}

// ======================================================================
// Flash attention, fp32, replacement mask (j <= i -> -1e9), no scaling.
// BR=BC=64, D=128, 256 threads. Last row-block processes ALL tiles so the
// fully-masked row N-1 gets the reference's uniform softmax exactly.
// ======================================================================
#define FBR 64
#define FBC 64
#define QSTR 129   // padded row stride for Q/K/V tiles (2-way max conflicts)
#define SSTR 65    // padded row stride for S tile

#define FLASH_SMEM_FLOATS (FBR*QSTR + FBC*QSTR + FBR*SSTR + 3*FBR)
#define FLASH_SMEM_BYTES  (FLASH_SMEM_FLOATS * 4)

__global__ __launch_bounds__(256)
void flash_attn(const float* __restrict__ Q, const float* __restrict__ K,
                const float* __restrict__ V, float* __restrict__ O)
{
    const int it = blockIdx.x;           // query row tile
    const int h  = blockIdx.y;           // head
    const int b  = blockIdx.z;           // batch
    const int g  = h & (CKVH - 1);       // kv head = h % KVH
    const int i0 = it * FBR;
    const int tid = threadIdx.x;

    extern __shared__ float sm[];
    float* Qs  = sm;                     // FBR x QSTR
    float* KVs = Qs + FBR*QSTR;          // FBC x QSTR (K then V)
    float* Ss  = KVs + FBC*QSTR;         // FBR x SSTR
    float* mS  = Ss + FBR*SSTR;          // FBR
    float* lS  = mS + FBR;               // FBR
    float* aS  = lS + FBR;               // FBR

    // ---- load Q tile (64 x 128), float4 ----
#pragma unroll
    for (int u = 0; u < 8; u++) {
        const int idx = tid + u * 256;       // float4 index 0..2047
        const int r  = idx >> 5;             // 32 float4 per row
        const int d4 = idx & 31;
        const float4 val = *reinterpret_cast<const float4*>(
            Q + (size_t)(b*CN + i0 + r) * CHD + h*CD + d4*4);
        float* dst = Qs + r*QSTR + d4*4;
        dst[0] = val.x; dst[1] = val.y; dst[2] = val.z; dst[3] = val.w;
    }
    if (tid < FBR) { mS[tid] = -INFINITY; lS[tid] = 0.0f; }

    const int sty = tid >> 4;   // S rows sty*4..+3
    const int stx = tid & 15;   // S cols stx*4..+3
    const int rg  = tid >> 4;   // O rows rg*4..+3
    const int cg  = tid & 15;   // O cols cg + 16*c (swizzled -> conflict-free LDS)

    float Oacc[4][8];
#pragma unroll
    for (int i = 0; i < 4; i++)
#pragma unroll
        for (int c = 0; c < 8; c++) Oacc[i][c] = 0.0f;

    const bool lastBlk = (i0 + FBR == CN);
    __syncthreads();

    for (int jc = 0; jc < CN; jc += FBC) {
        // skip fully-masked tiles (max j = jc+63 <= min i = i0), except in the
        // last row block where row N-1 needs every tile for its uniform softmax
        if (!lastBlk && (jc + FBC - 1) <= i0) continue;

        __syncthreads();   // previous PV (reads KVs) complete before overwrite

        // ---- load K tile ----
#pragma unroll
        for (int u = 0; u < 8; u++) {
            const int idx = tid + u * 256;
            const int r  = idx >> 5;
            const int d4 = idx & 31;
            const float4 val = *reinterpret_cast<const float4*>(
                K + (size_t)(b*CN + jc + r) * CKVD + g*CD + d4*4);
            float* dst = KVs + r*QSTR + d4*4;
            dst[0] = val.x; dst[1] = val.y; dst[2] = val.z; dst[3] = val.w;
        }
        __syncthreads();

        // ---- S = Q K^T (4x4 microtile) ----
        float sacc[4][4];
#pragma unroll
        for (int i = 0; i < 4; i++)
#pragma unroll
            for (int j = 0; j < 4; j++) sacc[i][j] = 0.0f;
#pragma unroll 4
        for (int d = 0; d < CD; d++) {
            float qv[4], kv[4];
#pragma unroll
            for (int i = 0; i < 4; i++) qv[i] = Qs[(sty*4 + i)*QSTR + d];
#pragma unroll
            for (int j = 0; j < 4; j++) kv[j] = KVs[(stx*4 + j)*QSTR + d];
#pragma unroll
            for (int i = 0; i < 4; i++)
#pragma unroll
                for (int j = 0; j < 4; j++)
                    sacc[i][j] += qv[i] * kv[j];
        }
        // mask (REPLACEMENT, matching jnp.where) + store to shared
#pragma unroll
        for (int i = 0; i < 4; i++) {
            const int gi = i0 + sty*4 + i;
#pragma unroll
            for (int j = 0; j < 4; j++) {
                const int gj = jc + stx*4 + j;
                Ss[(sty*4 + i)*SSTR + stx*4 + j] = (gj <= gi) ? -1e9f : sacc[i][j];
            }
        }
        __syncthreads();

        // ---- load V tile into KVs (K no longer needed) ----
#pragma unroll
        for (int u = 0; u < 8; u++) {
            const int idx = tid + u * 256;
            const int r  = idx >> 5;
            const int d4 = idx & 31;
            const float4 val = *reinterpret_cast<const float4*>(
                V + (size_t)(b*CN + jc + r) * CKVD + g*CD + d4*4);
            float* dst = KVs + r*QSTR + d4*4;
            dst[0] = val.x; dst[1] = val.y; dst[2] = val.z; dst[3] = val.w;
        }

        // ---- per-row online softmax stats (4 threads / row, same warp) ----
        {
            const int row = tid >> 2;
            const int q4  = tid & 3;
            float* srow = Ss + row*SSTR + q4*16;
            float mx = srow[0];
#pragma unroll
            for (int t = 1; t < 16; t++) mx = fmaxf(mx, srow[t]);
            mx = fmaxf(mx, __shfl_xor_sync(0xffffffffu, mx, 1));
            mx = fmaxf(mx, __shfl_xor_sync(0xffffffffu, mx, 2));
            const float mold = mS[row];
            const float mnew = fmaxf(mold, mx);
            float sum = 0.0f;
#pragma unroll
            for (int t = 0; t < 16; t++) {
                const float p = __expf(srow[t] - mnew);
                srow[t] = p;
                sum += p;
            }
            sum += __shfl_xor_sync(0xffffffffu, sum, 1);
            sum += __shfl_xor_sync(0xffffffffu, sum, 2);
            if (q4 == 0) {
                const float alpha = __expf(mold - mnew);   // exp(-inf)=0 first time
                aS[row] = alpha;
                mS[row] = mnew;
                lS[row] = lS[row] * alpha + sum;
            }
        }
        __syncthreads();

        // ---- rescale O, accumulate P @ V ----
        float al[4];
#pragma unroll
        for (int i = 0; i < 4; i++) al[i] = aS[rg*4 + i];
#pragma unroll
        for (int i = 0; i < 4; i++)
#pragma unroll
            for (int c = 0; c < 8; c++) Oacc[i][c] *= al[i];

#pragma unroll 2
        for (int j = 0; j < FBC; j++) {
            float pv[4];
#pragma unroll
            for (int i = 0; i < 4; i++) pv[i] = Ss[(rg*4 + i)*SSTR + j];
            float vv[8];
#pragma unroll
            for (int c = 0; c < 8; c++) vv[c] = KVs[j*QSTR + cg + 16*c];
#pragma unroll
            for (int i = 0; i < 4; i++)
#pragma unroll
                for (int c = 0; c < 8; c++)
                    Oacc[i][c] += pv[i] * vv[c];
        }
    }

    // ---- epilogue: O /= l, write [b, n, h*D + d] ----
    float linv[4];
#pragma unroll
    for (int i = 0; i < 4; i++) linv[i] = 1.0f / lS[rg*4 + i];
#pragma unroll
    for (int i = 0; i < 4; i++) {
        float* dst = O + (size_t)(b*CN + i0 + rg*4 + i) * CHD + h*CD + cg;
#pragma unroll
        for (int c = 0; c < 8; c++)
            dst[16*c] = Oacc[i][c] * linv[i];
    }
}

// ======================================================================
// launch
// ======================================================================
extern "C" void kernel_launch(void* const* d_in, const int* in_sizes, int n_in,
                              void* d_out, int out_size)
{
    const float* tokens = (const float*)d_in[0];
    const float* norm_w = (const float*)d_in[1];
    const float* Wq = (const float*)d_in[2];
    const float* bq = (const float*)d_in[3];
    const float* Wk = (const float*)d_in[4];
    const float* bk = (const float*)d_in[5];
    const float* Wv = (const float*)d_in[6];
    const float* bv = (const float*)d_in[7];
    const float* Wo = (const float*)d_in[8];
    const float* bo = (const float*)d_in[9];
    float* out = (float*)d_out;

    float* xn; cudaGetSymbolAddress((void**)&xn, g_xn);
    float* q;  cudaGetSymbolAddress((void**)&q,  g_q);
    float* k;  cudaGetSymbolAddress((void**)&k,  g_k);
    float* v;  cudaGetSymbolAddress((void**)&v,  g_v);
    float* a;  cudaGetSymbolAddress((void**)&a,  g_a);

    // 1. RMSNorm
    rmsnorm_kernel<<<CM, 256>>>(tokens, norm_w, xn);

    // 2. Projections (NT GEMMs)
    sgemm_nt<<<dim3(CHD/GBN,  CM/GBM), 256>>>(CM, CHD,  CHD, xn, Wq, bq, q);
    sgemm_nt<<<dim3(CKVD/GBN, CM/GBM), 256>>>(CM, CKVD, CHD, xn, Wk, bk, k);
    sgemm_nt<<<dim3(CKVD/GBN, CM/GBM), 256>>>(CM, CKVD, CHD, xn, Wv, bv, v);

    // 3. Flash attention
    cudaFuncSetAttribute(flash_attn, cudaFuncAttributeMaxDynamicSharedMemorySize,
                         FLASH_SMEM_BYTES);
    flash_attn<<<dim3(CN/FBR, CNH, CB), 256, FLASH_SMEM_BYTES>>>(q, k, v, a);

    // 4. Output projection -> d_out
    sgemm_nt<<<dim3(CHD/GBN, CM/GBM), 256>>>(CM, CHD, CHD, a, Wo, bo, out);
}

// round 6
// speedup vs baseline: 1.6600x; 1.6600x over previous
#include <cuda_runtime.h>
#include <cuda_bf16.h>
#include <math.h>
#include <stdint.h>

// ---------------- problem constants ----------------
#define CB   2
#define CN   2048
#define CHD  2048
#define CNH  16
#define CKVH 4
#define CD   128
#define CKVD 512
#define CM   (CB*CN)     // 4096 token rows
#define K2   (3*CHD)     // 6144: split-bf16 tripled K

// ---------------- scratch (device globals; no allocation allowed) ----------------
__device__ __nv_bfloat16 g_xn2[CM*K2];     // normed tokens, [hi, lo, hi] along K
__device__ __nv_bfloat16 g_wq2[CHD*K2];    // Wq, [hi, hi, lo]
__device__ __nv_bfloat16 g_wk2[CKVD*K2];
__device__ __nv_bfloat16 g_wv2[CKVD*K2];
__device__ __nv_bfloat16 g_wo2[CHD*K2];
__device__ float g_q [CM*CHD];
__device__ float g_k [CM*CKVD];
__device__ float g_v [CM*CKVD];
__device__ float g_a [CM*CHD];             // attention out (pre-Wo)
__device__ __nv_bfloat16 g_a2[CM*K2];      // attention out, [hi, lo, hi]

// ======================================================================
// helpers
// ======================================================================
__device__ __forceinline__ uint32_t smem_u32(const void* p) {
    uint32_t a;
    asm("{ .reg .u64 t; cvta.to.shared.u64 t, %1; cvt.u32.u64 %0, t; }" : "=r"(a) : "l"(p));
    return a;
}
#define CP_ASYNC16(dst, src) \
    asm volatile("cp.async.cg.shared.global [%0], [%1], 16;" :: "r"(dst), "l"(src))
#define CP_COMMIT() asm volatile("cp.async.commit_group;" ::: "memory")
#define CP_WAIT1()  asm volatile("cp.async.wait_group 1;" ::: "memory")
#define CP_WAIT0()  asm volatile("cp.async.wait_group 0;" ::: "memory")

__device__ __forceinline__ void ldm_x4(uint32_t& r0, uint32_t& r1, uint32_t& r2, uint32_t& r3,
                                       uint32_t addr) {
    asm volatile("ldmatrix.sync.aligned.m8n8.x4.shared.b16 {%0,%1,%2,%3}, [%4];"
                 : "=r"(r0), "=r"(r1), "=r"(r2), "=r"(r3) : "r"(addr));
}
__device__ __forceinline__ void mma_bf16(float c[4],
                                         uint32_t a0, uint32_t a1, uint32_t a2, uint32_t a3,
                                         uint32_t b0, uint32_t b1) {
    asm volatile("mma.sync.aligned.m16n8k16.row.col.f32.bf16.bf16.f32 "
                 "{%0,%1,%2,%3}, {%4,%5,%6,%7}, {%8,%9}, {%0,%1,%2,%3};"
                 : "+f"(c[0]), "+f"(c[1]), "+f"(c[2]), "+f"(c[3])
                 : "r"(a0), "r"(a1), "r"(a2), "r"(a3), "r"(b0), "r"(b1));
}

// ======================================================================
// RMSNorm fused with split-bf16 emit: row layout [hi(0:2048), lo, hi]
// ======================================================================
__global__ __launch_bounds__(256)
void rmsnorm_bf16(const float* __restrict__ x, const float* __restrict__ w,
                  __nv_bfloat16* __restrict__ y)
{
    const int row = blockIdx.x;
    const int tid = threadIdx.x;
    const float4* xr = reinterpret_cast<const float4*>(x + (size_t)row * CHD);
    float4 v0 = xr[tid];
    float4 v1 = xr[tid + 256];
    float ss = v0.x*v0.x + v0.y*v0.y + v0.z*v0.z + v0.w*v0.w
             + v1.x*v1.x + v1.y*v1.y + v1.z*v1.z + v1.w*v1.w;
#pragma unroll
    for (int o = 16; o > 0; o >>= 1) ss += __shfl_xor_sync(0xffffffffu, ss, o);
    __shared__ float red[8];
    if ((tid & 31) == 0) red[tid >> 5] = ss;
    __syncthreads();
    float tot = red[0]+red[1]+red[2]+red[3]+red[4]+red[5]+red[6]+red[7];
    const float sc = rsqrtf(tot * (1.0f / (float)CHD) + 1.1920929e-7f);

    const float4* wr = reinterpret_cast<const float4*>(w);
    __nv_bfloat16* yrow = y + (size_t)row * K2;

    float4 wv[2] = { wr[tid], wr[tid + 256] };
    float4 vv[2] = { v0, v1 };
#pragma unroll
    for (int h = 0; h < 2; h++) {
        const int k = 4 * (tid + h * 256);
        float e[4] = { vv[h].x*sc*wv[h].x, vv[h].y*sc*wv[h].y,
                       vv[h].z*sc*wv[h].z, vv[h].w*sc*wv[h].w };
        __nv_bfloat16 hi[4], lo[4];
#pragma unroll
        for (int j = 0; j < 4; j++) {
            hi[j] = __float2bfloat16(e[j]);
            lo[j] = __float2bfloat16(e[j] - __bfloat162float(hi[j]));
        }
        __nv_bfloat162 h01, h23, l01, l23;
        h01.x = hi[0]; h01.y = hi[1]; h23.x = hi[2]; h23.y = hi[3];
        l01.x = lo[0]; l01.y = lo[1]; l23.x = lo[2]; l23.y = lo[3];
        *reinterpret_cast<__nv_bfloat162*>(yrow + k)            = h01;
        *reinterpret_cast<__nv_bfloat162*>(yrow + k + 2)        = h23;
        *reinterpret_cast<__nv_bfloat162*>(yrow + CHD + k)      = l01;
        *reinterpret_cast<__nv_bfloat162*>(yrow + CHD + k + 2)  = l23;
        *reinterpret_cast<__nv_bfloat162*>(yrow + 2*CHD + k)    = h01;
        *reinterpret_cast<__nv_bfloat162*>(yrow + 2*CHD + k + 2)= h23;
    }
}

// ======================================================================
// split-bf16 conversion: lo_seg=2 -> [hi,hi,lo] (weights); =1 -> [hi,lo,hi]
// ======================================================================
__global__ __launch_bounds__(256)
void convert_split(const float* __restrict__ X, __nv_bfloat16* __restrict__ Y,
                   int total4, int lo_seg)
{
    const int stride = gridDim.x * blockDim.x;
    for (int i = blockIdx.x * blockDim.x + threadIdx.x; i < total4; i += stride) {
        float4 v = reinterpret_cast<const float4*>(X)[i];
        const int e0 = i * 4;
        const int r  = e0 / CHD;
        const int k  = e0 - r * CHD;
        __nv_bfloat16* yrow = Y + (size_t)r * K2;
        float e[4] = { v.x, v.y, v.z, v.w };
        __nv_bfloat16 hi[4], lo[4];
#pragma unroll
        for (int j = 0; j < 4; j++) {
            hi[j] = __float2bfloat16(e[j]);
            lo[j] = __float2bfloat16(e[j] - __bfloat162float(hi[j]));
        }
        __nv_bfloat162 h01, h23, l01, l23;
        h01.x = hi[0]; h01.y = hi[1]; h23.x = hi[2]; h23.y = hi[3];
        l01.x = lo[0]; l01.y = lo[1]; l23.x = lo[2]; l23.y = lo[3];
        const int hseg = (lo_seg == 1) ? 2 : 1;
        *reinterpret_cast<__nv_bfloat162*>(yrow + k)                  = h01;
        *reinterpret_cast<__nv_bfloat162*>(yrow + k + 2)              = h23;
        *reinterpret_cast<__nv_bfloat162*>(yrow + hseg*CHD + k)       = h01;
        *reinterpret_cast<__nv_bfloat162*>(yrow + hseg*CHD + k + 2)   = h23;
        *reinterpret_cast<__nv_bfloat162*>(yrow + lo_seg*CHD + k)     = l01;
        *reinterpret_cast<__nv_bfloat162*>(yrow + lo_seg*CHD + k + 2) = l23;
    }
}

// ======================================================================
// HMMA bf16 NT GEMM: C[M,Nout] = A[M,K2] @ B[Nout,K2]^T + bias
// 128x128 CTA tile, BK=64, 256 threads, mma.sync.m16n8k16 + ldmatrix +
// cp.async double buffering. Warp tile 64x32 (warps 2(M) x 4(N)).
// ======================================================================
#define BM 128
#define BN 128
#define BK 64
#define KP 72                         // padded bf16 stride (144 B rows)
#define TILE_ELEMS (128*KP)           // 9216 bf16 per buffer per tensor
#define NCHUNK (K2 / BK)              // 96
#define GSMEM_BYTES (4*TILE_ELEMS*2)  // A[2] + B[2] = 73728 B

__global__ __launch_bounds__(256)
void gemm_hmma(const __nv_bfloat16* __restrict__ A, const __nv_bfloat16* __restrict__ B,
               const float* __restrict__ bias, float* __restrict__ C, int Nout)
{
    extern __shared__ __nv_bfloat16 smem[];
    __nv_bfloat16* As = smem;                     // [2][128][KP]
    __nv_bfloat16* Bs = smem + 2 * TILE_ELEMS;    // [2][128][KP]
    const uint32_t sbA = smem_u32(As);
    const uint32_t sbB = smem_u32(Bs);

    const int tid  = threadIdx.x;
    const int lane = tid & 31;
    const int wid  = tid >> 5;
    const int wm   = wid & 1;      // 0..1
    const int wn   = wid >> 1;     // 0..3
    const int m0 = blockIdx.y * BM;
    const int n0 = blockIdx.x * BN;

    // loader indices: 1024 16B-chunks per tensor per k-chunk; 4 per thread
    const int lr = tid >> 3;       // row  (0..31 base; +32*u)
    const int lc = tid & 7;        // 16B col (0..7)

    const __nv_bfloat16* Ag = A + (size_t)(m0 + lr) * K2 + lc * 8;
    const __nv_bfloat16* Bg = B + (size_t)(n0 + lr) * K2 + lc * 8;
    const uint32_t sA_st = (uint32_t)((lr * KP + lc * 8) * 2);
    const uint32_t sB_st = sA_st;

    // ldmatrix per-lane addressing (element offsets within a buffer)
    const int g   = lane >> 3;     // 0..3 (matrix index)
    const int grw = lane & 7;      // row within 8x8 matrix
    // A: matrix order (m0-7,k0)(m8-15,k0)(m0-7,k8)(m8-15,k8)
    const int aRow = wm * 64 + (g & 1) * 8 + grw;   // + i*16
    const int aCol = (g >> 1) * 8;                   // + s*16
    // B: matrix order (n0-7,k0)(n0-7,k8)(n8-15,k0)(n8-15,k8)
    const int bRow = wn * 32 + (g >> 1) * 8 + grw;  // + p*16
    const int bCol = (g & 1) * 8;                    // + s*16

    float acc[4][4][4];
#pragma unroll
    for (int i = 0; i < 4; i++)
#pragma unroll
        for (int j = 0; j < 4; j++)
#pragma unroll
            for (int t = 0; t < 4; t++) acc[i][j][t] = 0.0f;

    // ---- prefetch chunk 0 ----
    {
        const uint32_t dA = sbA + sA_st;
        const uint32_t dB = sbB + sB_st;
#pragma unroll
        for (int u = 0; u < 4; u++) {
            CP_ASYNC16(dA + u * 32 * KP * 2, Ag + (size_t)(u * 32) * K2);
            CP_ASYNC16(dB + u * 32 * KP * 2, Bg + (size_t)(u * 32) * K2);
        }
        CP_COMMIT();
    }

    for (int kc = 0; kc < NCHUNK; kc++) {
        const int buf = kc & 1;
        if (kc + 1 < NCHUNK) {
            const int nb = (kc + 1) & 1;
            const uint32_t dA = sbA + nb * TILE_ELEMS * 2 + sA_st;
            const uint32_t dB = sbB + nb * TILE_ELEMS * 2 + sB_st;
            const __nv_bfloat16* Ap = Ag + (size_t)(kc + 1) * BK;
            const __nv_bfloat16* Bp = Bg + (size_t)(kc + 1) * BK;
#pragma unroll
            for (int u = 0; u < 4; u++) {
                CP_ASYNC16(dA + u * 32 * KP * 2, Ap + (size_t)(u * 32) * K2);
                CP_ASYNC16(dB + u * 32 * KP * 2, Bp + (size_t)(u * 32) * K2);
            }
            CP_COMMIT();
            CP_WAIT1();
        } else {
            CP_WAIT0();
        }
        __syncthreads();

        const uint32_t aBase = sbA + buf * TILE_ELEMS * 2;
        const uint32_t bBase = sbB + buf * TILE_ELEMS * 2;
#pragma unroll
        for (int s = 0; s < 4; s++) {
            uint32_t af[4][4];
#pragma unroll
            for (int i = 0; i < 4; i++) {
                const uint32_t addr = aBase +
                    (uint32_t)(((aRow + i * 16) * KP + aCol + s * 16) * 2);
                ldm_x4(af[i][0], af[i][1], af[i][2], af[i][3], addr);
            }
            uint32_t bf[2][4];
#pragma unroll
            for (int p = 0; p < 2; p++) {
                const uint32_t addr = bBase +
                    (uint32_t)(((bRow + p * 16) * KP + bCol + s * 16) * 2);
                ldm_x4(bf[p][0], bf[p][1], bf[p][2], bf[p][3], addr);
            }
#pragma unroll
            for (int i = 0; i < 4; i++)
#pragma unroll
                for (int j = 0; j < 4; j++) {
                    const int p = j >> 1, q = (j & 1) * 2;
                    mma_bf16(acc[i][j], af[i][0], af[i][1], af[i][2], af[i][3],
                             bf[p][q], bf[p][q + 1]);
                }
        }
        __syncthreads();
    }

    // ---- epilogue: bias + store fp32 ----
    const int row0 = m0 + wm * 64 + (lane >> 2);
    const int col0 = n0 + wn * 32 + 2 * (lane & 3);
#pragma unroll
    for (int j = 0; j < 4; j++) {
        const int c = col0 + j * 8;
        const float b0v = bias[c], b1v = bias[c + 1];
#pragma unroll
        for (int i = 0; i < 4; i++) {
            const int r = row0 + i * 16;
            float2 v;
            v.x = acc[i][j][0] + b0v; v.y = acc[i][j][1] + b1v;
            *reinterpret_cast<float2*>(C + (size_t)r * Nout + c) = v;
            v.x = acc[i][j][2] + b0v; v.y = acc[i][j][3] + b1v;
            *reinterpret_cast<float2*>(C + (size_t)(r + 8) * Nout + c) = v;
        }
    }
}

// ======================================================================
// Flash attention (unchanged, passing): fp32, replacement mask
// (j <= i -> -1e9), no scaling. BR=BC=64, D=128, 256 threads.
// ======================================================================
#define FBR 64
#define FBC 64
#define QSTR 129
#define SSTR 65
#define FLASH_SMEM_FLOATS (FBR*QSTR + FBC*QSTR + FBR*SSTR + 3*FBR)
#define FLASH_SMEM_BYTES  (FLASH_SMEM_FLOATS * 4)

__global__ __launch_bounds__(256)
void flash_attn(const float* __restrict__ Q, const float* __restrict__ K,
                const float* __restrict__ V, float* __restrict__ O)
{
    const int it = blockIdx.x;
    const int h  = blockIdx.y;
    const int b  = blockIdx.z;
    const int g  = h & (CKVH - 1);
    const int i0 = it * FBR;
    const int tid = threadIdx.x;

    extern __shared__ float sm[];
    float* Qs  = sm;
    float* KVs = Qs + FBR*QSTR;
    float* Ss  = KVs + FBC*QSTR;
    float* mS  = Ss + FBR*SSTR;
    float* lS  = mS + FBR;
    float* aS  = lS + FBR;

#pragma unroll
    for (int u = 0; u < 8; u++) {
        const int idx = tid + u * 256;
        const int r  = idx >> 5;
        const int d4 = idx & 31;
        const float4 val = *reinterpret_cast<const float4*>(
            Q + (size_t)(b*CN + i0 + r) * CHD + h*CD + d4*4);
        float* dst = Qs + r*QSTR + d4*4;
        dst[0] = val.x; dst[1] = val.y; dst[2] = val.z; dst[3] = val.w;
    }
    if (tid < FBR) { mS[tid] = -INFINITY; lS[tid] = 0.0f; }

    const int sty = tid >> 4;
    const int stx = tid & 15;
    const int rg  = tid >> 4;
    const int cg  = tid & 15;

    float Oacc[4][8];
#pragma unroll
    for (int i = 0; i < 4; i++)
#pragma unroll
        for (int c = 0; c < 8; c++) Oacc[i][c] = 0.0f;

    const bool lastBlk = (i0 + FBR == CN);
    __syncthreads();

    for (int jc = 0; jc < CN; jc += FBC) {
        if (!lastBlk && (jc + FBC - 1) <= i0) continue;

        __syncthreads();

#pragma unroll
        for (int u = 0; u < 8; u++) {
            const int idx = tid + u * 256;
            const int r  = idx >> 5;
            const int d4 = idx & 31;
            const float4 val = *reinterpret_cast<const float4*>(
                K + (size_t)(b*CN + jc + r) * CKVD + g*CD + d4*4);
            float* dst = KVs + r*QSTR + d4*4;
            dst[0] = val.x; dst[1] = val.y; dst[2] = val.z; dst[3] = val.w;
        }
        __syncthreads();

        float sacc[4][4];
#pragma unroll
        for (int i = 0; i < 4; i++)
#pragma unroll
            for (int j = 0; j < 4; j++) sacc[i][j] = 0.0f;
#pragma unroll 4
        for (int d = 0; d < CD; d++) {
            float qv[4], kv[4];
#pragma unroll
            for (int i = 0; i < 4; i++) qv[i] = Qs[(sty*4 + i)*QSTR + d];
#pragma unroll
            for (int j = 0; j < 4; j++) kv[j] = KVs[(stx*4 + j)*QSTR + d];
#pragma unroll
            for (int i = 0; i < 4; i++)
#pragma unroll
                for (int j = 0; j < 4; j++)
                    sacc[i][j] += qv[i] * kv[j];
        }
#pragma unroll
        for (int i = 0; i < 4; i++) {
            const int gi = i0 + sty*4 + i;
#pragma unroll
            for (int j = 0; j < 4; j++) {
                const int gj = jc + stx*4 + j;
                Ss[(sty*4 + i)*SSTR + stx*4 + j] = (gj <= gi) ? -1e9f : sacc[i][j];
            }
        }
        __syncthreads();

#pragma unroll
        for (int u = 0; u < 8; u++) {
            const int idx = tid + u * 256;
            const int r  = idx >> 5;
            const int d4 = idx & 31;
            const float4 val = *reinterpret_cast<const float4*>(
                V + (size_t)(b*CN + jc + r) * CKVD + g*CD + d4*4);
            float* dst = KVs + r*QSTR + d4*4;
            dst[0] = val.x; dst[1] = val.y; dst[2] = val.z; dst[3] = val.w;
        }

        {
            const int row = tid >> 2;
            const int q4  = tid & 3;
            float* srow = Ss + row*SSTR + q4*16;
            float mx = srow[0];
#pragma unroll
            for (int t = 1; t < 16; t++) mx = fmaxf(mx, srow[t]);
            mx = fmaxf(mx, __shfl_xor_sync(0xffffffffu, mx, 1));
            mx = fmaxf(mx, __shfl_xor_sync(0xffffffffu, mx, 2));
            const float mold = mS[row];
            const float mnew = fmaxf(mold, mx);
            float sum = 0.0f;
#pragma unroll
            for (int t = 0; t < 16; t++) {
                const float p = __expf(srow[t] - mnew);
                srow[t] = p;
                sum += p;
            }
            sum += __shfl_xor_sync(0xffffffffu, sum, 1);
            sum += __shfl_xor_sync(0xffffffffu, sum, 2);
            if (q4 == 0) {
                const float alpha = __expf(mold - mnew);
                aS[row] = alpha;
                mS[row] = mnew;
                lS[row] = lS[row] * alpha + sum;
            }
        }
        __syncthreads();

        float al[4];
#pragma unroll
        for (int i = 0; i < 4; i++) al[i] = aS[rg*4 + i];
#pragma unroll
        for (int i = 0; i < 4; i++)
#pragma unroll
            for (int c = 0; c < 8; c++) Oacc[i][c] *= al[i];

#pragma unroll 2
        for (int j = 0; j < FBC; j++) {
            float pv[4];
#pragma unroll
            for (int i = 0; i < 4; i++) pv[i] = Ss[(rg*4 + i)*SSTR + j];
            float vv[8];
#pragma unroll
            for (int c = 0; c < 8; c++) vv[c] = KVs[j*QSTR + cg + 16*c];
#pragma unroll
            for (int i = 0; i < 4; i++)
#pragma unroll
                for (int c = 0; c < 8; c++)
                    Oacc[i][c] += pv[i] * vv[c];
        }
    }

    float linv[4];
#pragma unroll
    for (int i = 0; i < 4; i++) linv[i] = 1.0f / lS[rg*4 + i];
#pragma unroll
    for (int i = 0; i < 4; i++) {
        float* dst = O + (size_t)(b*CN + i0 + rg*4 + i) * CHD + h*CD + cg;
#pragma unroll
        for (int c = 0; c < 8; c++)
            dst[16*c] = Oacc[i][c] * linv[i];
    }
}

// ======================================================================
// launch
// ======================================================================
extern "C" void kernel_launch(void* const* d_in, const int* in_sizes, int n_in,
                              void* d_out, int out_size)
{
    const float* tokens = (const float*)d_in[0];
    const float* norm_w = (const float*)d_in[1];
    const float* Wq = (const float*)d_in[2];
    const float* bq = (const float*)d_in[3];
    const float* Wk = (const float*)d_in[4];
    const float* bk = (const float*)d_in[5];
    const float* Wv = (const float*)d_in[6];
    const float* bv = (const float*)d_in[7];
    const float* Wo = (const float*)d_in[8];
    const float* bo = (const float*)d_in[9];
    float* out = (float*)d_out;

    __nv_bfloat16 *xn2, *wq2, *wk2, *wv2, *wo2, *a2;
    float *q, *k, *v, *a;
    cudaGetSymbolAddress((void**)&xn2, g_xn2);
    cudaGetSymbolAddress((void**)&wq2, g_wq2);
    cudaGetSymbolAddress((void**)&wk2, g_wk2);
    cudaGetSymbolAddress((void**)&wv2, g_wv2);
    cudaGetSymbolAddress((void**)&wo2, g_wo2);
    cudaGetSymbolAddress((void**)&a2,  g_a2);
    cudaGetSymbolAddress((void**)&q,   g_q);
    cudaGetSymbolAddress((void**)&k,   g_k);
    cudaGetSymbolAddress((void**)&v,   g_v);
    cudaGetSymbolAddress((void**)&a,   g_a);

    cudaFuncSetAttribute(gemm_hmma, cudaFuncAttributeMaxDynamicSharedMemorySize, GSMEM_BYTES);
    cudaFuncSetAttribute(flash_attn, cudaFuncAttributeMaxDynamicSharedMemorySize, FLASH_SMEM_BYTES);

    // 1. RMSNorm fused with split-bf16 emit
    rmsnorm_bf16<<<CM, 256>>>(tokens, norm_w, xn2);

    // 2. weight conversions (hi, hi, lo)
    convert_split<<<1024, 256>>>(Wq, wq2, CHD*CHD/4,  2);
    convert_split<<<512,  256>>>(Wk, wk2, CKVD*CHD/4, 2);
    convert_split<<<512,  256>>>(Wv, wv2, CKVD*CHD/4, 2);
    convert_split<<<1024, 256>>>(Wo, wo2, CHD*CHD/4,  2);

    // 3. projections via HMMA
    gemm_hmma<<<dim3(CHD/BN,  CM/BM), 256, GSMEM_BYTES>>>(xn2, wq2, bq, q, CHD);
    gemm_hmma<<<dim3(CKVD/BN, CM/BM), 256, GSMEM_BYTES>>>(xn2, wk2, bk, k, CKVD);
    gemm_hmma<<<dim3(CKVD/BN, CM/BM), 256, GSMEM_BYTES>>>(xn2, wv2, bv, v, CKVD);

    // 4. flash attention (fp32)
    flash_attn<<<dim3(CN/FBR, CNH, CB), 256, FLASH_SMEM_BYTES>>>(q, k, v, a);

    // 5. output projection
    convert_split<<<2048, 256>>>(a, a2, CM*CHD/4, 1);   // (hi, lo, hi)
    gemm_hmma<<<dim3(CHD/BN, CM/BM), 256, GSMEM_BYTES>>>(a2, wo2, bo, out, CHD);
}

// round 7
// speedup vs baseline: 3.0203x; 1.8195x over previous
#include <cuda_runtime.h>
#include <cuda_bf16.h>
#include <math.h>
#include <stdint.h>

// ---------------- problem constants ----------------
#define CB   2
#define CN   2048
#define CHD  2048
#define CNH  16
#define CKVH 4
#define CD   128
#define CKVD 512
#define CM   (CB*CN)     // 4096 token rows
#define K2   (3*CHD)     // 6144: split-bf16 tripled K

// ---------------- scratch (device globals; no allocation allowed) ----------------
__device__ __nv_bfloat16 g_xn2[CM*K2];     // normed tokens, [hi, lo, hi] along K
__device__ __nv_bfloat16 g_wq2[CHD*K2];    // Wq, [hi, hi, lo]
__device__ __nv_bfloat16 g_wkv2[1024*K2];  // [Wk; Wv] stacked, [hi, hi, lo]
__device__ __nv_bfloat16 g_wo2[CHD*K2];
__device__ float         g_bkv[1024];      // [bk; bv]
__device__ __nv_bfloat16 g_qh[CM*CHD];     // Q hi plane
__device__ __nv_bfloat16 g_ql[CM*CHD];     // Q lo plane
__device__ __nv_bfloat16 g_kvh[CM*1024];   // [K | V] hi plane
__device__ __nv_bfloat16 g_kvl[CM*1024];   // [K | V] lo plane
__device__ __nv_bfloat16 g_a2[CM*K2];      // attention out, [hi, lo, hi]

// ======================================================================
// helpers
// ======================================================================
__device__ __forceinline__ uint32_t smem_u32(const void* p) {
    uint32_t a;
    asm("{ .reg .u64 t; cvta.to.shared.u64 t, %1; cvt.u32.u64 %0, t; }" : "=r"(a) : "l"(p));
    return a;
}
#define CP_ASYNC16(dst, src) \
    asm volatile("cp.async.cg.shared.global [%0], [%1], 16;" :: "r"(dst), "l"(src))
#define CP_COMMIT() asm volatile("cp.async.commit_group;" ::: "memory")
#define CP_WAIT1()  asm volatile("cp.async.wait_group 1;" ::: "memory")
#define CP_WAIT0()  asm volatile("cp.async.wait_group 0;" ::: "memory")

__device__ __forceinline__ void ldm_x4(uint32_t& r0, uint32_t& r1, uint32_t& r2, uint32_t& r3,
                                       uint32_t addr) {
    asm volatile("ldmatrix.sync.aligned.m8n8.x4.shared.b16 {%0,%1,%2,%3}, [%4];"
                 : "=r"(r0), "=r"(r1), "=r"(r2), "=r"(r3) : "r"(addr));
}
__device__ __forceinline__ void ldm_x4_t(uint32_t& r0, uint32_t& r1, uint32_t& r2, uint32_t& r3,
                                         uint32_t addr) {
    asm volatile("ldmatrix.sync.aligned.m8n8.x4.trans.shared.b16 {%0,%1,%2,%3}, [%4];"
                 : "=r"(r0), "=r"(r1), "=r"(r2), "=r"(r3) : "r"(addr));
}
__device__ __forceinline__ void mma_bf16(float c[4],
                                         uint32_t a0, uint32_t a1, uint32_t a2, uint32_t a3,
                                         uint32_t b0, uint32_t b1) {
    asm volatile("mma.sync.aligned.m16n8k16.row.col.f32.bf16.bf16.f32 "
                 "{%0,%1,%2,%3}, {%4,%5,%6,%7}, {%8,%9}, {%0,%1,%2,%3};"
                 : "+f"(c[0]), "+f"(c[1]), "+f"(c[2]), "+f"(c[3])
                 : "r"(a0), "r"(a1), "r"(a2), "r"(a3), "r"(b0), "r"(b1));
}
// split a float pair into packed bf16 hi pair + lo pair
__device__ __forceinline__ void split2(float x, float y, uint32_t& hi, uint32_t& lo) {
    __nv_bfloat162 H, L;
    H.x = __float2bfloat16(x); H.y = __float2bfloat16(y);
    L.x = __float2bfloat16(x - __bfloat162float(H.x));
    L.y = __float2bfloat16(y - __bfloat162float(H.y));
    hi = *reinterpret_cast<uint32_t*>(&H);
    lo = *reinterpret_cast<uint32_t*>(&L);
}

// ======================================================================
// RMSNorm fused with split-bf16 emit: row layout [hi(0:2048), lo, hi]
// ======================================================================
__global__ __launch_bounds__(256)
void rmsnorm_bf16(const float* __restrict__ x, const float* __restrict__ w,
                  __nv_bfloat16* __restrict__ y)
{
    const int row = blockIdx.x;
    const int tid = threadIdx.x;
    const float4* xr = reinterpret_cast<const float4*>(x + (size_t)row * CHD);
    float4 v0 = xr[tid];
    float4 v1 = xr[tid + 256];
    float ss = v0.x*v0.x + v0.y*v0.y + v0.z*v0.z + v0.w*v0.w
             + v1.x*v1.x + v1.y*v1.y + v1.z*v1.z + v1.w*v1.w;
#pragma unroll
    for (int o = 16; o > 0; o >>= 1) ss += __shfl_xor_sync(0xffffffffu, ss, o);
    __shared__ float red[8];
    if ((tid & 31) == 0) red[tid >> 5] = ss;
    __syncthreads();
    float tot = red[0]+red[1]+red[2]+red[3]+red[4]+red[5]+red[6]+red[7];
    const float sc = rsqrtf(tot * (1.0f / (float)CHD) + 1.1920929e-7f);

    const float4* wr = reinterpret_cast<const float4*>(w);
    __nv_bfloat16* yrow = y + (size_t)row * K2;

    float4 wv[2] = { wr[tid], wr[tid + 256] };
    float4 vv[2] = { v0, v1 };
#pragma unroll
    for (int h = 0; h < 2; h++) {
        const int k = 4 * (tid + h * 256);
        float e[4] = { vv[h].x*sc*wv[h].x, vv[h].y*sc*wv[h].y,
                       vv[h].z*sc*wv[h].z, vv[h].w*sc*wv[h].w };
        uint32_t h01, l01, h23, l23;
        split2(e[0], e[1], h01, l01);
        split2(e[2], e[3], h23, l23);
        *reinterpret_cast<uint32_t*>(yrow + k)             = h01;
        *reinterpret_cast<uint32_t*>(yrow + k + 2)         = h23;
        *reinterpret_cast<uint32_t*>(yrow + CHD + k)       = l01;
        *reinterpret_cast<uint32_t*>(yrow + CHD + k + 2)   = l23;
        *reinterpret_cast<uint32_t*>(yrow + 2*CHD + k)     = h01;
        *reinterpret_cast<uint32_t*>(yrow + 2*CHD + k + 2) = h23;
    }
}

// ======================================================================
// split-bf16 weight conversion -> [hi, hi, lo] layout, row stride K2
// ======================================================================
__global__ __launch_bounds__(256)
void convert_w(const float* __restrict__ X, __nv_bfloat16* __restrict__ Y, int total4)
{
    const int stride = gridDim.x * blockDim.x;
    for (int i = blockIdx.x * blockDim.x + threadIdx.x; i < total4; i += stride) {
        float4 v = reinterpret_cast<const float4*>(X)[i];
        const int e0 = i * 4;
        const int r  = e0 / CHD;
        const int k  = e0 - r * CHD;
        __nv_bfloat16* yrow = Y + (size_t)r * K2;
        uint32_t h01, l01, h23, l23;
        split2(v.x, v.y, h01, l01);
        split2(v.z, v.w, h23, l23);
        *reinterpret_cast<uint32_t*>(yrow + k)             = h01;
        *reinterpret_cast<uint32_t*>(yrow + k + 2)         = h23;
        *reinterpret_cast<uint32_t*>(yrow + CHD + k)       = h01;
        *reinterpret_cast<uint32_t*>(yrow + CHD + k + 2)   = h23;
        *reinterpret_cast<uint32_t*>(yrow + 2*CHD + k)     = l01;
        *reinterpret_cast<uint32_t*>(yrow + 2*CHD + k + 2) = l23;
    }
}

__global__ void concat_bias(const float* __restrict__ bk, const float* __restrict__ bv,
                            float* __restrict__ bkv)
{
    int i = threadIdx.x + blockIdx.x * blockDim.x;
    if (i < 512) bkv[i] = bk[i];
    else if (i < 1024) bkv[i] = bv[i - 512];
}

// ======================================================================
// HMMA bf16 NT GEMM: 128x128 CTA tile, BK=64, 256 threads, cp.async x2.
// mode 0: C = fp32 (+bias). mode 1: write split bf16 planes Chi/Clo (+bias).
// ======================================================================
#define BM 128
#define BN 128
#define BK 64
#define KP 72
#define TILE_ELEMS (128*KP)
#define NCHUNK (K2 / BK)
#define GSMEM_BYTES (4*TILE_ELEMS*2)

__global__ __launch_bounds__(256)
void gemm_hmma(const __nv_bfloat16* __restrict__ A, const __nv_bfloat16* __restrict__ B,
               const float* __restrict__ bias,
               float* __restrict__ Cf,
               __nv_bfloat16* __restrict__ Chi, __nv_bfloat16* __restrict__ Clo,
               int Nout, int mode)
{
    extern __shared__ __nv_bfloat16 smem[];
    __nv_bfloat16* As = smem;
    __nv_bfloat16* Bs = smem + 2 * TILE_ELEMS;
    const uint32_t sbA = smem_u32(As);
    const uint32_t sbB = smem_u32(Bs);

    const int tid  = threadIdx.x;
    const int lane = tid & 31;
    const int wid  = tid >> 5;
    const int wm   = wid & 1;
    const int wn   = wid >> 1;
    const int m0 = blockIdx.y * BM;
    const int n0 = blockIdx.x * BN;

    const int lr = tid >> 3;
    const int lc = tid & 7;

    const __nv_bfloat16* Ag = A + (size_t)(m0 + lr) * K2 + lc * 8;
    const __nv_bfloat16* Bg = B + (size_t)(n0 + lr) * K2 + lc * 8;
    const uint32_t sA_st = (uint32_t)((lr * KP + lc * 8) * 2);

    const int g   = lane >> 3;
    const int grw = lane & 7;
    const int aRow = wm * 64 + (g & 1) * 8 + grw;
    const int aCol = (g >> 1) * 8;
    const int bRow = wn * 32 + (g >> 1) * 8 + grw;
    const int bCol = (g & 1) * 8;

    float acc[4][4][4];
#pragma unroll
    for (int i = 0; i < 4; i++)
#pragma unroll
        for (int j = 0; j < 4; j++)
#pragma unroll
            for (int t = 0; t < 4; t++) acc[i][j][t] = 0.0f;

    {
        const uint32_t dA = sbA + sA_st;
        const uint32_t dB = sbB + sA_st;
#pragma unroll
        for (int u = 0; u < 4; u++) {
            CP_ASYNC16(dA + u * 32 * KP * 2, Ag + (size_t)(u * 32) * K2);
            CP_ASYNC16(dB + u * 32 * KP * 2, Bg + (size_t)(u * 32) * K2);
        }
        CP_COMMIT();
    }

    for (int kc = 0; kc < NCHUNK; kc++) {
        const int buf = kc & 1;
        if (kc + 1 < NCHUNK) {
            const int nb = (kc + 1) & 1;
            const uint32_t dA = sbA + nb * TILE_ELEMS * 2 + sA_st;
            const uint32_t dB = sbB + nb * TILE_ELEMS * 2 + sA_st;
            const __nv_bfloat16* Ap = Ag + (size_t)(kc + 1) * BK;
            const __nv_bfloat16* Bp = Bg + (size_t)(kc + 1) * BK;
#pragma unroll
            for (int u = 0; u < 4; u++) {
                CP_ASYNC16(dA + u * 32 * KP * 2, Ap + (size_t)(u * 32) * K2);
                CP_ASYNC16(dB + u * 32 * KP * 2, Bp + (size_t)(u * 32) * K2);
            }
            CP_COMMIT();
            CP_WAIT1();
        } else {
            CP_WAIT0();
        }
        __syncthreads();

        const uint32_t aBase = sbA + buf * TILE_ELEMS * 2;
        const uint32_t bBase = sbB + buf * TILE_ELEMS * 2;
#pragma unroll
        for (int s = 0; s < 4; s++) {
            uint32_t af[4][4];
#pragma unroll
            for (int i = 0; i < 4; i++) {
                const uint32_t addr = aBase +
                    (uint32_t)(((aRow + i * 16) * KP + aCol + s * 16) * 2);
                ldm_x4(af[i][0], af[i][1], af[i][2], af[i][3], addr);
            }
            uint32_t bf[2][4];
#pragma unroll
            for (int p = 0; p < 2; p++) {
                const uint32_t addr = bBase +
                    (uint32_t)(((bRow + p * 16) * KP + bCol + s * 16) * 2);
                ldm_x4(bf[p][0], bf[p][1], bf[p][2], bf[p][3], addr);
            }
#pragma unroll
            for (int i = 0; i < 4; i++)
#pragma unroll
                for (int j = 0; j < 4; j++) {
                    const int p = j >> 1, q = (j & 1) * 2;
                    mma_bf16(acc[i][j], af[i][0], af[i][1], af[i][2], af[i][3],
                             bf[p][q], bf[p][q + 1]);
                }
        }
        __syncthreads();
    }

    const int row0 = m0 + wm * 64 + (lane >> 2);
    const int col0 = n0 + wn * 32 + 2 * (lane & 3);
#pragma unroll
    for (int j = 0; j < 4; j++) {
        const int c = col0 + j * 8;
        const float b0v = bias[c], b1v = bias[c + 1];
#pragma unroll
        for (int i = 0; i < 4; i++) {
            const int r = row0 + i * 16;
            float v0 = acc[i][j][0] + b0v, v1 = acc[i][j][1] + b1v;
            float v2 = acc[i][j][2] + b0v, v3 = acc[i][j][3] + b1v;
            if (mode == 0) {
                float2 o;
                o.x = v0; o.y = v1;
                *reinterpret_cast<float2*>(Cf + (size_t)r * Nout + c) = o;
                o.x = v2; o.y = v3;
                *reinterpret_cast<float2*>(Cf + (size_t)(r + 8) * Nout + c) = o;
            } else {
                uint32_t hi, lo;
                split2(v0, v1, hi, lo);
                *reinterpret_cast<uint32_t*>(Chi + (size_t)r * Nout + c) = hi;
                *reinterpret_cast<uint32_t*>(Clo + (size_t)r * Nout + c) = lo;
                split2(v2, v3, hi, lo);
                *reinterpret_cast<uint32_t*>(Chi + (size_t)(r + 8) * Nout + c) = hi;
                *reinterpret_cast<uint32_t*>(Clo + (size_t)(r + 8) * Nout + c) = lo;
            }
        }
    }
}

// ======================================================================
// HMMA flash attention. BR=128, BC=64, D=128, 256 threads (8 warps),
// split-bf16 3-pass for both QK^T and PV. Replacement mask (j<=i -> -1e9),
// no 1/sqrt(D). Writes output directly in [hi,lo,hi] K2 layout.
// ======================================================================
#define ABR 128
#define ABC 64
#define AST 136
#define SQH 0
#define SQL (128*AST)
#define SKV0 (2*128*AST)
#define KVPL (64*AST)
#define KVBUF (4*KVPL)
#define FA_SMEM_BYTES ((SKV0 + 2*KVBUF) * 2)   // 208896

__global__ __launch_bounds__(256)
void flash_hmma(const __nv_bfloat16* __restrict__ Qh, const __nv_bfloat16* __restrict__ Ql,
                const __nv_bfloat16* __restrict__ KVh, const __nv_bfloat16* __restrict__ KVl,
                __nv_bfloat16* __restrict__ A2)
{
    const int it = blockIdx.x;
    const int h  = blockIdx.y;
    const int b  = blockIdx.z;
    const int g  = h & (CKVH - 1);
    const int i0 = it * ABR;
    const int tid = threadIdx.x;
    const int lane = tid & 31;
    const int wid = tid >> 5;

    extern __shared__ __nv_bfloat16 sm[];
    const uint32_t sb = smem_u32(sm);

    // ---- Q load (both planes), plain vector loads ----
    {
        const size_t qbase = (size_t)(b*CN + i0) * CHD + h*CD;
#pragma unroll
        for (int u = 0; u < 8; u++) {
            const int idx = tid + u * 256;
            const int r = idx >> 4, c8 = idx & 15;
            *reinterpret_cast<uint4*>(&sm[SQH + r*AST + c8*8]) =
                *reinterpret_cast<const uint4*>(Qh + qbase + (size_t)r*CHD + c8*8);
            *reinterpret_cast<uint4*>(&sm[SQL + r*AST + c8*8]) =
                *reinterpret_cast<const uint4*>(Ql + qbase + (size_t)r*CHD + c8*8);
        }
    }

    const bool lastBlk = (i0 + ABR == CN);
    const int jstart = lastBlk ? 0 : i0;
    const int ntiles = (CN - jstart) / ABC;

    // ---- KV tile loader (cp.async) ----
    auto load_kv = [&](int jc, int bf) {
        const size_t kbase = (size_t)(b*CN + jc) * 1024 + g*CD;
        const size_t vbase = kbase + 512;
        const uint32_t d0 = sb + (uint32_t)(SKV0 + bf*KVBUF) * 2;
#pragma unroll
        for (int u = 0; u < 4; u++) {
            const int idx = tid + u * 256;
            const int r = idx >> 4, c8 = idx & 15;
            const uint32_t so = (uint32_t)((r*AST + c8*8) * 2);
            const size_t go = (size_t)r * 1024 + c8*8;
            CP_ASYNC16(d0 + so,              KVh + kbase + go);
            CP_ASYNC16(d0 + KVPL*2 + so,     KVl + kbase + go);
            CP_ASYNC16(d0 + 2*KVPL*2 + so,   KVh + vbase + go);
            CP_ASYNC16(d0 + 3*KVPL*2 + so,   KVl + vbase + go);
        }
        CP_COMMIT();
    };

    load_kv(jstart, 0);

    // fragment addressing
    const int gmt = lane >> 3, grw = lane & 7;
    const int aRow = wid*16 + (gmt & 1)*8 + grw;       // A-frag rows (Q / P)
    const int aColB = (gmt >> 1) * 8;
    const int bRowB = (gmt >> 1)*8 + grw;              // B-frag rows (K, NT)
    const int bColB = (gmt & 1) * 8;
    const int tRow = (gmt & 1)*8 + grw;                // trans B-frag rows (V)
    const int tCol = (gmt >> 1) * 8;

    const int r1 = i0 + wid*16 + (lane >> 2);
    const int r2 = r1 + 8;

    float oa[16][4];
#pragma unroll
    for (int n = 0; n < 16; n++)
#pragma unroll
        for (int t = 0; t < 4; t++) oa[n][t] = 0.0f;
    float m1 = -INFINITY, m2 = -INFINITY, l1 = 0.0f, l2 = 0.0f;

    for (int t = 0; t < ntiles; t++) {
        const int jc = jstart + t * ABC;
        const int bf = t & 1;
        if (t + 1 < ntiles) {
            load_kv(jc + ABC, (t + 1) & 1);
            CP_WAIT1();
        } else {
            CP_WAIT0();
        }
        __syncthreads();

        const uint32_t kB = sb + (uint32_t)(SKV0 + bf*KVBUF) * 2;

        // ---- S = Q K^T, 3-pass split ----
        float sa[8][4];
#pragma unroll
        for (int n = 0; n < 8; n++)
#pragma unroll
            for (int q = 0; q < 4; q++) sa[n][q] = 0.0f;

#pragma unroll
        for (int s = 0; s < 8; s++) {
            uint32_t qh[4], ql[4];
            ldm_x4(qh[0], qh[1], qh[2], qh[3],
                   sb + (uint32_t)((SQH + aRow*AST + aColB + s*16) * 2));
            ldm_x4(ql[0], ql[1], ql[2], ql[3],
                   sb + (uint32_t)((SQL + aRow*AST + aColB + s*16) * 2));
#pragma unroll
            for (int nt = 0; nt < 4; nt++) {
                uint32_t kh[4], kl[4];
                const uint32_t ko = (uint32_t)(((nt*16 + bRowB)*AST + bColB + s*16) * 2);
                ldm_x4(kh[0], kh[1], kh[2], kh[3], kB + ko);
                ldm_x4(kl[0], kl[1], kl[2], kl[3], kB + KVPL*2 + ko);
                mma_bf16(sa[2*nt],   qh[0], qh[1], qh[2], qh[3], kh[0], kh[1]);
                mma_bf16(sa[2*nt],   ql[0], ql[1], ql[2], ql[3], kh[0], kh[1]);
                mma_bf16(sa[2*nt],   qh[0], qh[1], qh[2], qh[3], kl[0], kl[1]);
                mma_bf16(sa[2*nt+1], qh[0], qh[1], qh[2], qh[3], kh[2], kh[3]);
                mma_bf16(sa[2*nt+1], ql[0], ql[1], ql[2], ql[3], kh[2], kh[3]);
                mma_bf16(sa[2*nt+1], qh[0], qh[1], qh[2], qh[3], kl[2], kl[3]);
            }
        }

        // ---- mask (replacement) ----
        if (jc < i0 + ABR) {
#pragma unroll
            for (int n = 0; n < 8; n++) {
                const int c0 = jc + n*8 + (lane & 3)*2;
#pragma unroll
                for (int q = 0; q < 2; q++) {
                    if (c0 + q <= r1) sa[n][q]     = -1e9f;
                    if (c0 + q <= r2) sa[n][2 + q] = -1e9f;
                }
            }
        }

        // ---- online softmax (register + quad shuffles) ----
        float mx1 = -INFINITY, mx2 = -INFINITY;
#pragma unroll
        for (int n = 0; n < 8; n++) {
            mx1 = fmaxf(mx1, fmaxf(sa[n][0], sa[n][1]));
            mx2 = fmaxf(mx2, fmaxf(sa[n][2], sa[n][3]));
        }
        mx1 = fmaxf(mx1, __shfl_xor_sync(0xffffffffu, mx1, 1));
        mx1 = fmaxf(mx1, __shfl_xor_sync(0xffffffffu, mx1, 2));
        mx2 = fmaxf(mx2, __shfl_xor_sync(0xffffffffu, mx2, 1));
        mx2 = fmaxf(mx2, __shfl_xor_sync(0xffffffffu, mx2, 2));
        const float mn1 = fmaxf(m1, mx1);
        const float mn2 = fmaxf(m2, mx2);
        const float al1 = __expf(m1 - mn1);
        const float al2 = __expf(m2 - mn2);
        m1 = mn1; m2 = mn2;

        float sum1 = 0.0f, sum2 = 0.0f;
#pragma unroll
        for (int n = 0; n < 8; n++) {
            sa[n][0] = __expf(sa[n][0] - mn1); sum1 += sa[n][0];
            sa[n][1] = __expf(sa[n][1] - mn1); sum1 += sa[n][1];
            sa[n][2] = __expf(sa[n][2] - mn2); sum2 += sa[n][2];
            sa[n][3] = __expf(sa[n][3] - mn2); sum2 += sa[n][3];
        }
        sum1 += __shfl_xor_sync(0xffffffffu, sum1, 1);
        sum1 += __shfl_xor_sync(0xffffffffu, sum1, 2);
        sum2 += __shfl_xor_sync(0xffffffffu, sum2, 1);
        sum2 += __shfl_xor_sync(0xffffffffu, sum2, 2);
        l1 = l1 * al1 + sum1;
        l2 = l2 * al2 + sum2;

#pragma unroll
        for (int n = 0; n < 16; n++) {
            oa[n][0] *= al1; oa[n][1] *= al1;
            oa[n][2] *= al2; oa[n][3] *= al2;
        }

        // ---- O += P V, 3-pass split ----
        const uint32_t vhB = kB + 2*KVPL*2;
        const uint32_t vlB = kB + 3*KVPL*2;
#pragma unroll
        for (int kt = 0; kt < 4; kt++) {
            uint32_t ph[4], pl[4];
            split2(sa[2*kt][0],   sa[2*kt][1],   ph[0], pl[0]);
            split2(sa[2*kt][2],   sa[2*kt][3],   ph[1], pl[1]);
            split2(sa[2*kt+1][0], sa[2*kt+1][1], ph[2], pl[2]);
            split2(sa[2*kt+1][2], sa[2*kt+1][3], ph[3], pl[3]);
#pragma unroll
            for (int nt = 0; nt < 8; nt++) {
                uint32_t vh[4], vl[4];
                const uint32_t vo = (uint32_t)(((kt*16 + tRow)*AST + nt*16 + tCol) * 2);
                ldm_x4_t(vh[0], vh[1], vh[2], vh[3], vhB + vo);
                ldm_x4_t(vl[0], vl[1], vl[2], vl[3], vlB + vo);
                mma_bf16(oa[2*nt],   ph[0], ph[1], ph[2], ph[3], vh[0], vh[1]);
                mma_bf16(oa[2*nt],   pl[0], pl[1], pl[2], pl[3], vh[0], vh[1]);
                mma_bf16(oa[2*nt],   ph[0], ph[1], ph[2], ph[3], vl[0], vl[1]);
                mma_bf16(oa[2*nt+1], ph[0], ph[1], ph[2], ph[3], vh[2], vh[3]);
                mma_bf16(oa[2*nt+1], pl[0], pl[1], pl[2], pl[3], vh[2], vh[3]);
                mma_bf16(oa[2*nt+1], ph[0], ph[1], ph[2], ph[3], vl[2], vl[3]);
            }
        }
        __syncthreads();   // all warps done with buffer bf before overwrite
    }

    // ---- epilogue: O /= l, write split [hi, lo, hi] into A2 ----
    const float li1 = 1.0f / l1;
    const float li2 = 1.0f / l2;
    __nv_bfloat16* row1p = A2 + (size_t)(b*CN + r1) * K2;
    __nv_bfloat16* row2p = A2 + (size_t)(b*CN + r2) * K2;
#pragma unroll
    for (int n = 0; n < 16; n++) {
        const int col = h*CD + n*8 + (lane & 3)*2;
        uint32_t hi, lo;
        split2(oa[n][0] * li1, oa[n][1] * li1, hi, lo);
        *reinterpret_cast<uint32_t*>(row1p + col)         = hi;
        *reinterpret_cast<uint32_t*>(row1p + CHD + col)   = lo;
        *reinterpret_cast<uint32_t*>(row1p + 2*CHD + col) = hi;
        split2(oa[n][2] * li2, oa[n][3] * li2, hi, lo);
        *reinterpret_cast<uint32_t*>(row2p + col)         = hi;
        *reinterpret_cast<uint32_t*>(row2p + CHD + col)   = lo;
        *reinterpret_cast<uint32_t*>(row2p + 2*CHD + col) = hi;
    }
}

// ======================================================================
// launch
// ======================================================================
extern "C" void kernel_launch(void* const* d_in, const int* in_sizes, int n_in,
                              void* d_out, int out_size)
{
    const float* tokens = (const float*)d_in[0];
    const float* norm_w = (const float*)d_in[1];
    const float* Wq = (const float*)d_in[2];
    const float* bq = (const float*)d_in[3];
    const float* Wk = (const float*)d_in[4];
    const float* bk = (const float*)d_in[5];
    const float* Wv = (const float*)d_in[6];
    const float* bv = (const float*)d_in[7];
    const float* Wo = (const float*)d_in[8];
    const float* bo = (const float*)d_in[9];
    float* out = (float*)d_out;

    __nv_bfloat16 *xn2, *wq2, *wkv2, *wo2, *qh, *ql, *kvh, *kvl, *a2;
    float* bkv;
    cudaGetSymbolAddress((void**)&xn2,  g_xn2);
    cudaGetSymbolAddress((void**)&wq2,  g_wq2);
    cudaGetSymbolAddress((void**)&wkv2, g_wkv2);
    cudaGetSymbolAddress((void**)&wo2,  g_wo2);
    cudaGetSymbolAddress((void**)&bkv,  g_bkv);
    cudaGetSymbolAddress((void**)&qh,   g_qh);
    cudaGetSymbolAddress((void**)&ql,   g_ql);
    cudaGetSymbolAddress((void**)&kvh,  g_kvh);
    cudaGetSymbolAddress((void**)&kvl,  g_kvl);
    cudaGetSymbolAddress((void**)&a2,   g_a2);

    cudaFuncSetAttribute(gemm_hmma, cudaFuncAttributeMaxDynamicSharedMemorySize, GSMEM_BYTES);
    cudaFuncSetAttribute(flash_hmma, cudaFuncAttributeMaxDynamicSharedMemorySize, FA_SMEM_BYTES);

    // 1. RMSNorm -> split bf16 activations
    rmsnorm_bf16<<<CM, 256>>>(tokens, norm_w, xn2);

    // 2. weight conversions + bias concat
    convert_w<<<1024, 256>>>(Wq, wq2, CHD*CHD/4);
    convert_w<<<512,  256>>>(Wk, wkv2, CKVD*CHD/4);
    convert_w<<<512,  256>>>(Wv, wkv2 + (size_t)512*K2, CKVD*CHD/4);
    convert_w<<<1024, 256>>>(Wo, wo2, CHD*CHD/4);
    concat_bias<<<4, 256>>>(bk, bv, bkv);

    // 3. Q and fused K|V projections -> split bf16 planes
    gemm_hmma<<<dim3(CHD/BN,  CM/BM), 256, GSMEM_BYTES>>>(xn2, wq2,  bq,  nullptr, qh,  ql,  CHD,  1);
    gemm_hmma<<<dim3(1024/BN, CM/BM), 256, GSMEM_BYTES>>>(xn2, wkv2, bkv, nullptr, kvh, kvl, 1024, 1);

    // 4. HMMA flash attention -> a2 ([hi,lo,hi] layout)
    flash_hmma<<<dim3(CN/ABR, CNH, CB), 256, FA_SMEM_BYTES>>>(qh, ql, kvh, kvl, a2);

    // 5. output projection -> d_out (fp32)
    gemm_hmma<<<dim3(CHD/BN, CM/BM), 256, GSMEM_BYTES>>>(a2, wo2, bo, out, nullptr, nullptr, CHD, 0);
}

// round 9
// speedup vs baseline: 3.0395x; 1.0064x over previous
#include <cuda_runtime.h>
#include <cuda_bf16.h>
#include <math.h>
#include <stdint.h>

// ---------------- problem constants ----------------
#define CB   2
#define CN   2048
#define CHD  2048
#define CNH  16
#define CKVH 4
#define CD   128
#define CKVD 512
#define CM   (CB*CN)     // 4096 token rows
#define K2   (3*CHD)     // 6144: split-bf16 tripled K

// ---------------- scratch (device globals; no allocation allowed) ----------------
__device__ __nv_bfloat16 g_xn2[CM*K2];      // normed tokens, [hi, lo, hi] along K
__device__ __nv_bfloat16 g_wqkv2[3072*K2];  // [Wq; Wk; Wv] stacked, [hi, hi, lo]
__device__ __nv_bfloat16 g_wo2[CHD*K2];
__device__ float         g_bqkv[3072];      // [bq; bk; bv]
__device__ __nv_bfloat16 g_qh[CM*CHD];      // Q hi plane
__device__ __nv_bfloat16 g_ql[CM*CHD];      // Q lo plane
__device__ __nv_bfloat16 g_kvh[CM*1024];    // [K | V] hi plane
__device__ __nv_bfloat16 g_kvl[CM*1024];    // [K | V] lo plane
__device__ __nv_bfloat16 g_a2[CM*K2];       // attention out, [hi, lo, hi]

// ======================================================================
// helpers
// ======================================================================
__device__ __forceinline__ uint32_t smem_u32(const void* p) {
    uint32_t a;
    asm("{ .reg .u64 t; cvta.to.shared.u64 t, %1; cvt.u32.u64 %0, t; }" : "=r"(a) : "l"(p));
    return a;
}
#define CP_ASYNC16(dst, src) \
    asm volatile("cp.async.cg.shared.global [%0], [%1], 16;" :: "r"(dst), "l"(src))
#define CP_COMMIT() asm volatile("cp.async.commit_group;" ::: "memory")
#define CP_WAIT2()  asm volatile("cp.async.wait_group 2;" ::: "memory")
#define CP_WAIT1()  asm volatile("cp.async.wait_group 1;" ::: "memory")
#define CP_WAIT0()  asm volatile("cp.async.wait_group 0;" ::: "memory")

__device__ __forceinline__ void ldm_x4(uint32_t& r0, uint32_t& r1, uint32_t& r2, uint32_t& r3,
                                       uint32_t addr) {
    asm volatile("ldmatrix.sync.aligned.m8n8.x4.shared.b16 {%0,%1,%2,%3}, [%4];"
                 : "=r"(r0), "=r"(r1), "=r"(r2), "=r"(r3) : "r"(addr));
}
__device__ __forceinline__ void ldm_x4_t(uint32_t& r0, uint32_t& r1, uint32_t& r2, uint32_t& r3,
                                         uint32_t addr) {
    asm volatile("ldmatrix.sync.aligned.m8n8.x4.trans.shared.b16 {%0,%1,%2,%3}, [%4];"
                 : "=r"(r0), "=r"(r1), "=r"(r2), "=r"(r3) : "r"(addr));
}
__device__ __forceinline__ void mma_bf16(float c[4],
                                         uint32_t a0, uint32_t a1, uint32_t a2, uint32_t a3,
                                         uint32_t b0, uint32_t b1) {
    asm volatile("mma.sync.aligned.m16n8k16.row.col.f32.bf16.bf16.f32 "
                 "{%0,%1,%2,%3}, {%4,%5,%6,%7}, {%8,%9}, {%0,%1,%2,%3};"
                 : "+f"(c[0]), "+f"(c[1]), "+f"(c[2]), "+f"(c[3])
                 : "r"(a0), "r"(a1), "r"(a2), "r"(a3), "r"(b0), "r"(b1));
}
__device__ __forceinline__ void split2(float x, float y, uint32_t& hi, uint32_t& lo) {
    __nv_bfloat162 H, L;
    H.x = __float2bfloat16(x); H.y = __float2bfloat16(y);
    L.x = __float2bfloat16(x - __bfloat162float(H.x));
    L.y = __float2bfloat16(y - __bfloat162float(H.y));
    hi = *reinterpret_cast<uint32_t*>(&H);
    lo = *reinterpret_cast<uint32_t*>(&L);
}

// ======================================================================
// RMSNorm fused with split-bf16 emit: row layout [hi(0:2048), lo, hi]
// ======================================================================
__global__ __launch_bounds__(256)
void rmsnorm_bf16(const float* __restrict__ x, const float* __restrict__ w,
                  __nv_bfloat16* __restrict__ y)
{
    const int row = blockIdx.x;
    const int tid = threadIdx.x;
    const float4* xr = reinterpret_cast<const float4*>(x + (size_t)row * CHD);
    float4 v0 = xr[tid];
    float4 v1 = xr[tid + 256];
    float ss = v0.x*v0.x + v0.y*v0.y + v0.z*v0.z + v0.w*v0.w
             + v1.x*v1.x + v1.y*v1.y + v1.z*v1.z + v1.w*v1.w;
#pragma unroll
    for (int o = 16; o > 0; o >>= 1) ss += __shfl_xor_sync(0xffffffffu, ss, o);
    __shared__ float red[8];
    if ((tid & 31) == 0) red[tid >> 5] = ss;
    __syncthreads();
    float tot = red[0]+red[1]+red[2]+red[3]+red[4]+red[5]+red[6]+red[7];
    const float sc = rsqrtf(tot * (1.0f / (float)CHD) + 1.1920929e-7f);

    const float4* wr = reinterpret_cast<const float4*>(w);
    __nv_bfloat16* yrow = y + (size_t)row * K2;

    float4 wv[2] = { wr[tid], wr[tid + 256] };
    float4 vv[2] = { v0, v1 };
#pragma unroll
    for (int h = 0; h < 2; h++) {
        const int k = 4 * (tid + h * 256);
        float e[4] = { vv[h].x*sc*wv[h].x, vv[h].y*sc*wv[h].y,
                       vv[h].z*sc*wv[h].z, vv[h].w*sc*wv[h].w };
        uint32_t h01, l01, h23, l23;
        split2(e[0], e[1], h01, l01);
        split2(e[2], e[3], h23, l23);
        *reinterpret_cast<uint32_t*>(yrow + k)             = h01;
        *reinterpret_cast<uint32_t*>(yrow + k + 2)         = h23;
        *reinterpret_cast<uint32_t*>(yrow + CHD + k)       = l01;
        *reinterpret_cast<uint32_t*>(yrow + CHD + k + 2)   = l23;
        *reinterpret_cast<uint32_t*>(yrow + 2*CHD + k)     = h01;
        *reinterpret_cast<uint32_t*>(yrow + 2*CHD + k + 2) = h23;
    }
}

// ======================================================================
// split-bf16 weight conversion -> [hi, hi, lo] layout, row stride K2
// ======================================================================
__global__ __launch_bounds__(256)
void convert_w(const float* __restrict__ X, __nv_bfloat16* __restrict__ Y, int total4)
{
    const int stride = gridDim.x * blockDim.x;
    for (int i = blockIdx.x * blockDim.x + threadIdx.x; i < total4; i += stride) {
        float4 v = reinterpret_cast<const float4*>(X)[i];
        const int e0 = i * 4;
        const int r  = e0 / CHD;
        const int k  = e0 - r * CHD;
        __nv_bfloat16* yrow = Y + (size_t)r * K2;
        uint32_t h01, l01, h23, l23;
        split2(v.x, v.y, h01, l01);
        split2(v.z, v.w, h23, l23);
        *reinterpret_cast<uint32_t*>(yrow + k)             = h01;
        *reinterpret_cast<uint32_t*>(yrow + k + 2)         = h23;
        *reinterpret_cast<uint32_t*>(yrow + CHD + k)       = h01;
        *reinterpret_cast<uint32_t*>(yrow + CHD + k + 2)   = h23;
        *reinterpret_cast<uint32_t*>(yrow + 2*CHD + k)     = l01;
        *reinterpret_cast<uint32_t*>(yrow + 2*CHD + k + 2) = l23;
    }
}

__global__ void concat_bias3(const float* __restrict__ bq, const float* __restrict__ bk,
                             const float* __restrict__ bv, float* __restrict__ bqkv)
{
    int i = threadIdx.x + blockIdx.x * blockDim.x;
    if (i < 2048) bqkv[i] = bq[i];
    else if (i < 2560) bqkv[i] = bk[i - 2048];
    else if (i < 3072) bqkv[i] = bv[i - 2560];
}

// ======================================================================
// HMMA bf16 NT GEMM: 128x256 CTA tile, BK=64, 3-stage cp.async, 256 thr,
// warp tile 64x64 (2x4 warp grid).
// mode 0: C = fp32 (+bias) into Cf[*,2048].
// mode 1: QKV epilogue: n<2048 -> qh/ql[*,2048]; else -> kvh/kvl[*,1024], col n-2048.
// ======================================================================
#define BM 128
#define BN 256
#define BK 64
#define KP 72
#define ATILE (BM*KP)
#define BTILE (BN*KP)
#define STAGE (ATILE+BTILE)           // 27648 elems
#define NCHUNK (K2 / BK)              // 96
#define GSMEM_BYTES (3*STAGE*2)       // 165888

__global__ __launch_bounds__(256, 1)
void gemm_hmma(const __nv_bfloat16* __restrict__ A, const __nv_bfloat16* __restrict__ B,
               const float* __restrict__ bias,
               float* __restrict__ Cf,
               __nv_bfloat16* __restrict__ Qhp, __nv_bfloat16* __restrict__ Qlp,
               __nv_bfloat16* __restrict__ KVhp, __nv_bfloat16* __restrict__ KVlp,
               int mode)
{
    extern __shared__ __nv_bfloat16 smem[];
    const uint32_t sb = smem_u32(smem);

    const int tid  = threadIdx.x;
    const int lane = tid & 31;
    const int wid  = tid >> 5;
    const int wm   = wid & 1;
    const int wn   = wid >> 1;
    const int m0 = blockIdx.y * BM;
    const int n0 = blockIdx.x * BN;

    // loaders
    const int r0 = tid >> 3;          // 0..31
    const int c0 = tid & 7;           // 16B column
    const __nv_bfloat16* Ag = A + (size_t)(m0 + r0) * K2 + c0 * 8;
    const __nv_bfloat16* Bg = B + (size_t)(n0 + r0) * K2 + c0 * 8;
    const uint32_t sA_st = (uint32_t)((r0 * KP + c0 * 8) * 2);

    auto issue = [&](int kc) {
        const int st = kc % 3;
        const uint32_t aD = sb + (uint32_t)(st * STAGE) * 2 + sA_st;
        const uint32_t bD = sb + (uint32_t)(st * STAGE + ATILE) * 2 + sA_st;
        const __nv_bfloat16* Ap = Ag + (size_t)kc * BK;
        const __nv_bfloat16* Bp = Bg + (size_t)kc * BK;
#pragma unroll
        for (int u = 0; u < 4; u++)
            CP_ASYNC16(aD + u * 32 * KP * 2, Ap + (size_t)(u * 32) * K2);
#pragma unroll
        for (int u = 0; u < 8; u++)
            CP_ASYNC16(bD + u * 32 * KP * 2, Bp + (size_t)(u * 32) * K2);
        CP_COMMIT();
    };

    // fragment addressing
    const int g   = lane >> 3;
    const int grw = lane & 7;
    const int aRow = wm * 64 + (g & 1) * 8 + grw;    // + i*16
    const int aCol = (g >> 1) * 8;                   // + s*16
    const int bRow = wn * 64 + (g >> 1) * 8 + grw;   // + p*16
    const int bCol = (g & 1) * 8;                    // + s*16

    float acc[4][8][4];
#pragma unroll
    for (int i = 0; i < 4; i++)
#pragma unroll
        for (int j = 0; j < 8; j++)
#pragma unroll
            for (int t = 0; t < 4; t++) acc[i][j][t] = 0.0f;

    issue(0);
    issue(1);

    for (int kc = 0; kc < NCHUNK; kc++) {
        if (kc + 2 < NCHUNK) { issue(kc + 2); CP_WAIT2(); }
        else if (kc + 1 < NCHUNK) { CP_WAIT1(); }
        else { CP_WAIT0(); }
        __syncthreads();

        const int st = kc % 3;
        const uint32_t aBase = sb + (uint32_t)(st * STAGE) * 2;
        const uint32_t bBase = sb + (uint32_t)(st * STAGE + ATILE) * 2;
#pragma unroll
        for (int s = 0; s < 4; s++) {
            uint32_t af[4][4];
#pragma unroll
            for (int i = 0; i < 4; i++)
                ldm_x4(af[i][0], af[i][1], af[i][2], af[i][3],
                       aBase + (uint32_t)(((aRow + i * 16) * KP + aCol + s * 16) * 2));
            uint32_t bf[4][4];
#pragma unroll
            for (int p = 0; p < 4; p++)
                ldm_x4(bf[p][0], bf[p][1], bf[p][2], bf[p][3],
                       bBase + (uint32_t)(((bRow + p * 16) * KP + bCol + s * 16) * 2));
#pragma unroll
            for (int i = 0; i < 4; i++)
#pragma unroll
                for (int j = 0; j < 8; j++) {
                    const int p = j >> 1, q = (j & 1) * 2;
                    mma_bf16(acc[i][j], af[i][0], af[i][1], af[i][2], af[i][3],
                             bf[p][q], bf[p][q + 1]);
                }
        }
        __syncthreads();
    }

    // ---- epilogue ----
    const int rowb = m0 + wm * 64 + (lane >> 2);
    const int colb = n0 + wn * 64 + 2 * (lane & 3);
#pragma unroll
    for (int j = 0; j < 8; j++) {
        const int c = colb + j * 8;
        const float b0v = bias[c], b1v = bias[c + 1];
#pragma unroll
        for (int i = 0; i < 4; i++) {
            const int r = rowb + i * 16;
            float v0 = acc[i][j][0] + b0v, v1 = acc[i][j][1] + b1v;
            float v2 = acc[i][j][2] + b0v, v3 = acc[i][j][3] + b1v;
            if (mode == 0) {
                float2 o;
                o.x = v0; o.y = v1;
                *reinterpret_cast<float2*>(Cf + (size_t)r * CHD + c) = o;
                o.x = v2; o.y = v3;
                *reinterpret_cast<float2*>(Cf + (size_t)(r + 8) * CHD + c) = o;
            } else {
                __nv_bfloat16 *Hp, *Lp;
                size_t off1, off2;
                if (c < 2048) {
                    Hp = Qhp; Lp = Qlp;
                    off1 = (size_t)r * CHD + c;
                    off2 = (size_t)(r + 8) * CHD + c;
                } else {
                    Hp = KVhp; Lp = KVlp;
                    off1 = (size_t)r * 1024 + (c - 2048);
                    off2 = (size_t)(r + 8) * 1024 + (c - 2048);
                }
                uint32_t hi, lo;
                split2(v0, v1, hi, lo);
                *reinterpret_cast<uint32_t*>(Hp + off1) = hi;
                *reinterpret_cast<uint32_t*>(Lp + off1) = lo;
                split2(v2, v3, hi, lo);
                *reinterpret_cast<uint32_t*>(Hp + off2) = hi;
                *reinterpret_cast<uint32_t*>(Lp + off2) = lo;
            }
        }
    }
}

// ======================================================================
// HMMA flash attention. BR=128, BC=64, D=128, 256 threads (8 warps),
// split-bf16 3-pass for QK^T and PV. Replacement mask (j<=i -> -1e9).
// Every block processes only tiles jc >= i0; row N-1 is fixed up after.
// ======================================================================
#define ABR 128
#define ABC 64
#define AST 136
#define SQH 0
#define SQL (128*AST)
#define SKV0 (2*128*AST)
#define KVPL (64*AST)
#define KVBUF (4*KVPL)
#define FA_SMEM_BYTES ((SKV0 + 2*KVBUF) * 2)   // 208896

__global__ __launch_bounds__(256)
void flash_hmma(const __nv_bfloat16* __restrict__ Qh, const __nv_bfloat16* __restrict__ Ql,
                const __nv_bfloat16* __restrict__ KVh, const __nv_bfloat16* __restrict__ KVl,
                __nv_bfloat16* __restrict__ A2)
{
    const int it = blockIdx.x;
    const int h  = blockIdx.y;
    const int b  = blockIdx.z;
    const int g  = h & (CKVH - 1);
    const int i0 = it * ABR;
    const int tid = threadIdx.x;
    const int lane = tid & 31;
    const int wid = tid >> 5;

    extern __shared__ __nv_bfloat16 sm[];
    const uint32_t sb = smem_u32(sm);

    {
        const size_t qbase = (size_t)(b*CN + i0) * CHD + h*CD;
#pragma unroll
        for (int u = 0; u < 8; u++) {
            const int idx = tid + u * 256;
            const int r = idx >> 4, c8 = idx & 15;
            *reinterpret_cast<uint4*>(&sm[SQH + r*AST + c8*8]) =
                *reinterpret_cast<const uint4*>(Qh + qbase + (size_t)r*CHD + c8*8);
            *reinterpret_cast<uint4*>(&sm[SQL + r*AST + c8*8]) =
                *reinterpret_cast<const uint4*>(Ql + qbase + (size_t)r*CHD + c8*8);
        }
    }

    const int jstart = i0;
    const int ntiles = (CN - jstart) / ABC;

    auto load_kv = [&](int jc, int bf) {
        const size_t kbase = (size_t)(b*CN + jc) * 1024 + g*CD;
        const size_t vbase = kbase + 512;
        const uint32_t d0 = sb + (uint32_t)(SKV0 + bf*KVBUF) * 2;
#pragma unroll
        for (int u = 0; u < 4; u++) {
            const int idx = tid + u * 256;
            const int r = idx >> 4, c8 = idx & 15;
            const uint32_t so = (uint32_t)((r*AST + c8*8) * 2);
            const size_t go = (size_t)r * 1024 + c8*8;
            CP_ASYNC16(d0 + so,              KVh + kbase + go);
            CP_ASYNC16(d0 + KVPL*2 + so,     KVl + kbase + go);
            CP_ASYNC16(d0 + 2*KVPL*2 + so,   KVh + vbase + go);
            CP_ASYNC16(d0 + 3*KVPL*2 + so,   KVl + vbase + go);
        }
        CP_COMMIT();
    };

    load_kv(jstart, 0);

    const int gmt = lane >> 3, grw = lane & 7;
    const int aRow = wid*16 + (gmt & 1)*8 + grw;
    const int aColB = (gmt >> 1) * 8;
    const int bRowB = (gmt >> 1)*8 + grw;
    const int bColB = (gmt & 1) * 8;
    const int tRow = (gmt & 1)*8 + grw;
    const int tCol = (gmt >> 1) * 8;

    const int r1 = i0 + wid*16 + (lane >> 2);
    const int r2 = r1 + 8;

    float oa[16][4];
#pragma unroll
    for (int n = 0; n < 16; n++)
#pragma unroll
        for (int t = 0; t < 4; t++) oa[n][t] = 0.0f;
    float m1 = -INFINITY, m2 = -INFINITY, l1 = 0.0f, l2 = 0.0f;

    for (int t = 0; t < ntiles; t++) {
        const int jc = jstart + t * ABC;
        const int bf = t & 1;
        if (t + 1 < ntiles) {
            load_kv(jc + ABC, (t + 1) & 1);
            CP_WAIT1();
        } else {
            CP_WAIT0();
        }
        __syncthreads();

        const uint32_t kB = sb + (uint32_t)(SKV0 + bf*KVBUF) * 2;

        float sa[8][4];
#pragma unroll
        for (int n = 0; n < 8; n++)
#pragma unroll
            for (int q = 0; q < 4; q++) sa[n][q] = 0.0f;

#pragma unroll
        for (int s = 0; s < 8; s++) {
            uint32_t qh[4], ql[4];
            ldm_x4(qh[0], qh[1], qh[2], qh[3],
                   sb + (uint32_t)((SQH + aRow*AST + aColB + s*16) * 2));
            ldm_x4(ql[0], ql[1], ql[2], ql[3],
                   sb + (uint32_t)((SQL + aRow*AST + aColB + s*16) * 2));
#pragma unroll
            for (int nt = 0; nt < 4; nt++) {
                uint32_t kh[4], kl[4];
                const uint32_t ko = (uint32_t)(((nt*16 + bRowB)*AST + bColB + s*16) * 2);
                ldm_x4(kh[0], kh[1], kh[2], kh[3], kB + ko);
                ldm_x4(kl[0], kl[1], kl[2], kl[3], kB + KVPL*2 + ko);
                mma_bf16(sa[2*nt],   qh[0], qh[1], qh[2], qh[3], kh[0], kh[1]);
                mma_bf16(sa[2*nt],   ql[0], ql[1], ql[2], ql[3], kh[0], kh[1]);
                mma_bf16(sa[2*nt],   qh[0], qh[1], qh[2], qh[3], kl[0], kl[1]);
                mma_bf16(sa[2*nt+1], qh[0], qh[1], qh[2], qh[3], kh[2], kh[3]);
                mma_bf16(sa[2*nt+1], ql[0], ql[1], ql[2], ql[3], kh[2], kh[3]);
                mma_bf16(sa[2*nt+1], qh[0], qh[1], qh[2], qh[3], kl[2], kl[3]);
            }
        }

        if (jc < i0 + ABR) {
#pragma unroll
            for (int n = 0; n < 8; n++) {
                const int c0 = jc + n*8 + (lane & 3)*2;
#pragma unroll
                for (int q = 0; q < 2; q++) {
                    if (c0 + q <= r1) sa[n][q]     = -1e9f;
                    if (c0 + q <= r2) sa[n][2 + q] = -1e9f;
                }
            }
        }

        float mx1 = -INFINITY, mx2 = -INFINITY;
#pragma unroll
        for (int n = 0; n < 8; n++) {
            mx1 = fmaxf(mx1, fmaxf(sa[n][0], sa[n][1]));
            mx2 = fmaxf(mx2, fmaxf(sa[n][2], sa[n][3]));
        }
        mx1 = fmaxf(mx1, __shfl_xor_sync(0xffffffffu, mx1, 1));
        mx1 = fmaxf(mx1, __shfl_xor_sync(0xffffffffu, mx1, 2));
        mx2 = fmaxf(mx2, __shfl_xor_sync(0xffffffffu, mx2, 1));
        mx2 = fmaxf(mx2, __shfl_xor_sync(0xffffffffu, mx2, 2));
        const float mn1 = fmaxf(m1, mx1);
        const float mn2 = fmaxf(m2, mx2);
        const float al1 = __expf(m1 - mn1);
        const float al2 = __expf(m2 - mn2);
        m1 = mn1; m2 = mn2;

        float sum1 = 0.0f, sum2 = 0.0f;
#pragma unroll
        for (int n = 0; n < 8; n++) {
            sa[n][0] = __expf(sa[n][0] - mn1); sum1 += sa[n][0];
            sa[n][1] = __expf(sa[n][1] - mn1); sum1 += sa[n][1];
            sa[n][2] = __expf(sa[n][2] - mn2); sum2 += sa[n][2];
            sa[n][3] = __expf(sa[n][3] - mn2); sum2 += sa[n][3];
        }
        sum1 += __shfl_xor_sync(0xffffffffu, sum1, 1);
        sum1 += __shfl_xor_sync(0xffffffffu, sum1, 2);
        sum2 += __shfl_xor_sync(0xffffffffu, sum2, 1);
        sum2 += __shfl_xor_sync(0xffffffffu, sum2, 2);
        l1 = l1 * al1 + sum1;
        l2 = l2 * al2 + sum2;

#pragma unroll
        for (int n = 0; n < 16; n++) {
            oa[n][0] *= al1; oa[n][1] *= al1;
            oa[n][2] *= al2; oa[n][3] *= al2;
        }

        const uint32_t vhB = kB + 2*KVPL*2;
        const uint32_t vlB = kB + 3*KVPL*2;
#pragma unroll
        for (int kt = 0; kt < 4; kt++) {
            uint32_t ph[4], pl[4];
            split2(sa[2*kt][0],   sa[2*kt][1],   ph[0], pl[0]);
            split2(sa[2*kt][2],   sa[2*kt][3],   ph[1], pl[1]);
            split2(sa[2*kt+1][0], sa[2*kt+1][1], ph[2], pl[2]);
            split2(sa[2*kt+1][2], sa[2*kt+1][3], ph[3], pl[3]);
#pragma unroll
            for (int nt = 0; nt < 8; nt++) {
                uint32_t vh[4], vl[4];
                const uint32_t vo = (uint32_t)(((kt*16 + tRow)*AST + nt*16 + tCol) * 2);
                ldm_x4_t(vh[0], vh[1], vh[2], vh[3], vhB + vo);
                ldm_x4_t(vl[0], vl[1], vl[2], vl[3], vlB + vo);
                mma_bf16(oa[2*nt],   ph[0], ph[1], ph[2], ph[3], vh[0], vh[1]);
                mma_bf16(oa[2*nt],   pl[0], pl[1], pl[2], pl[3], vh[0], vh[1]);
                mma_bf16(oa[2*nt],   ph[0], ph[1], ph[2], ph[3], vl[0], vl[1]);
                mma_bf16(oa[2*nt+1], ph[0], ph[1], ph[2], ph[3], vh[2], vh[3]);
                mma_bf16(oa[2*nt+1], pl[0], pl[1], pl[2], pl[3], vh[2], vh[3]);
                mma_bf16(oa[2*nt+1], ph[0], ph[1], ph[2], ph[3], vl[2], vl[3]);
            }
        }
        __syncthreads();
    }

    const float li1 = 1.0f / l1;
    const float li2 = 1.0f / l2;
    __nv_bfloat16* row1p = A2 + (size_t)(b*CN + r1) * K2;
    __nv_bfloat16* row2p = A2 + (size_t)(b*CN + r2) * K2;
#pragma unroll
    for (int n = 0; n < 16; n++) {
        const int col = h*CD + n*8 + (lane & 3)*2;
        uint32_t hi, lo;
        split2(oa[n][0] * li1, oa[n][1] * li1, hi, lo);
        *reinterpret_cast<uint32_t*>(row1p + col)         = hi;
        *reinterpret_cast<uint32_t*>(row1p + CHD + col)   = lo;
        *reinterpret_cast<uint32_t*>(row1p + 2*CHD + col) = hi;
        split2(oa[n][2] * li2, oa[n][3] * li2, hi, lo);
        *reinterpret_cast<uint32_t*>(row2p + col)         = hi;
        *reinterpret_cast<uint32_t*>(row2p + CHD + col)   = lo;
        *reinterpret_cast<uint32_t*>(row2p + 2*CHD + col) = hi;
    }
}

// ======================================================================
// Row N-1 fixup: fully-masked row -> uniform softmax over ALL keys ->
// output = mean(V). Overwrites row 2047 of each batch in A2.
// grid (CB, CKVH), 128 threads (one per d).
// ======================================================================
__global__ __launch_bounds__(128)
void fix_last_row(const __nv_bfloat16* __restrict__ KVh,
                  const __nv_bfloat16* __restrict__ KVl,
                  __nv_bfloat16* __restrict__ A2)
{
    const int b = blockIdx.x;
    const int g = blockIdx.y;
    const int d = threadIdx.x;
    const __nv_bfloat16* vh = KVh + (size_t)(b*CN) * 1024 + 512 + g*CD + d;
    const __nv_bfloat16* vl = KVl + (size_t)(b*CN) * 1024 + 512 + g*CD + d;
    float s = 0.0f;
    for (int j = 0; j < CN; j++) {
        s += __bfloat162float(vh[(size_t)j * 1024]) + __bfloat162float(vl[(size_t)j * 1024]);
    }
    s *= (1.0f / (float)CN);
    __nv_bfloat16 hi = __float2bfloat16(s);
    __nv_bfloat16 lo = __float2bfloat16(s - __bfloat162float(hi));
    __nv_bfloat16* rowp = A2 + (size_t)(b*CN + CN - 1) * K2;
#pragma unroll
    for (int hh = 0; hh < 4; hh++) {
        const int h = hh * CKVH + g;       // heads with h % KVH == g
        const int col = h*CD + d;
        rowp[col]         = hi;
        rowp[CHD + col]   = lo;
        rowp[2*CHD + col] = hi;
    }
}

// ======================================================================
// launch
// ======================================================================
extern "C" void kernel_launch(void* const* d_in, const int* in_sizes, int n_in,
                              void* d_out, int out_size)
{
    const float* tokens = (const float*)d_in[0];
    const float* norm_w = (const float*)d_in[1];
    const float* Wq = (const float*)d_in[2];
    const float* bq = (const float*)d_in[3];
    const float* Wk = (const float*)d_in[4];
    const float* bk = (const float*)d_in[5];
    const float* Wv = (const float*)d_in[6];
    const float* bv = (const float*)d_in[7];
    const float* Wo = (const float*)d_in[8];
    const float* bo = (const float*)d_in[9];
    float* out = (float*)d_out;

    __nv_bfloat16 *xn2, *wqkv2, *wo2, *qh, *ql, *kvh, *kvl, *a2;
    float* bqkv;
    cudaGetSymbolAddress((void**)&xn2,   g_xn2);
    cudaGetSymbolAddress((void**)&wqkv2, g_wqkv2);
    cudaGetSymbolAddress((void**)&wo2,   g_wo2);
    cudaGetSymbolAddress((void**)&bqkv,  g_bqkv);
    cudaGetSymbolAddress((void**)&qh,    g_qh);
    cudaGetSymbolAddress((void**)&ql,    g_ql);
    cudaGetSymbolAddress((void**)&kvh,   g_kvh);
    cudaGetSymbolAddress((void**)&kvl,   g_kvl);
    cudaGetSymbolAddress((void**)&a2,    g_a2);

    cudaFuncSetAttribute(gemm_hmma, cudaFuncAttributeMaxDynamicSharedMemorySize, GSMEM_BYTES);
    cudaFuncSetAttribute(flash_hmma, cudaFuncAttributeMaxDynamicSharedMemorySize, FA_SMEM_BYTES);

    // 1. RMSNorm -> split bf16 activations
    rmsnorm_bf16<<<CM, 256>>>(tokens, norm_w, xn2);

    // 2. weight conversions + bias concat ([Wq; Wk; Wv] stacked)
    convert_w<<<1024, 256>>>(Wq, wqkv2, CHD*CHD/4);
    convert_w<<<512,  256>>>(Wk, wqkv2 + (size_t)2048*K2, CKVD*CHD/4);
    convert_w<<<512,  256>>>(Wv, wqkv2 + (size_t)2560*K2, CKVD*CHD/4);
    convert_w<<<1024, 256>>>(Wo, wo2, CHD*CHD/4);
    concat_bias3<<<12, 256>>>(bq, bk, bv, bqkv);

    // 3. fused QKV projection -> split bf16 planes
    gemm_hmma<<<dim3(3072/BN, CM/BM), 256, GSMEM_BYTES>>>(
        xn2, wqkv2, bqkv, nullptr, qh, ql, kvh, kvl, 1);

    // 4. HMMA flash attention -> a2 ([hi,lo,hi]), then fix row N-1
    flash_hmma<<<dim3(CN/ABR, CNH, CB), 256, FA_SMEM_BYTES>>>(qh, ql, kvh, kvl, a2);
    fix_last_row<<<dim3(CB, CKVH), 128>>>(kvh, kvl, a2);

    // 5. output projection -> d_out (fp32)
    gemm_hmma<<<dim3(CHD/BN, CM/BM), 256, GSMEM_BYTES>>>(
        a2, wo2, bo, out, nullptr, nullptr, nullptr, nullptr, 0);
}

// round 12
// speedup vs baseline: 3.3784x; 1.1115x over previous
#include <cuda_runtime.h>
#include <cuda_bf16.h>
#include <math.h>
#include <stdint.h>

// ---------------- problem constants ----------------
#define CB   2
#define CN   2048
#define CHD  2048
#define CNH  16
#define CKVH 4
#define CD   128
#define CKVD 512
#define CM   (CB*CN)     // 4096 token rows

// ---------------- scratch (device globals; no allocation allowed) ----------------
__device__ __nv_bfloat16 g_xnh[CM*CHD];     // normed tokens hi plane
__device__ __nv_bfloat16 g_xnl[CM*CHD];     // normed tokens lo plane
__device__ __nv_bfloat16 g_wqkvh[3072*CHD]; // [Wq; Wk; Wv] hi
__device__ __nv_bfloat16 g_wqkvl[3072*CHD]; // [Wq; Wk; Wv] lo
__device__ __nv_bfloat16 g_woh[CHD*CHD];
__device__ __nv_bfloat16 g_wol[CHD*CHD];
__device__ float         g_bqkv[3072];
__device__ __nv_bfloat16 g_qh[CM*CHD];      // Q hi
__device__ __nv_bfloat16 g_ql[CM*CHD];      // Q lo
__device__ __nv_bfloat16 g_kvh[CM*1024];    // [K | V] hi
__device__ __nv_bfloat16 g_kvl[CM*1024];    // [K | V] lo
__device__ __nv_bfloat16 g_ah[CM*CHD];      // attention out hi
__device__ __nv_bfloat16 g_al[CM*CHD];      // attention out lo

// ======================================================================
// helpers
// ======================================================================
__device__ __forceinline__ uint32_t smem_u32(const void* p) {
    uint32_t a;
    asm("{ .reg .u64 t; cvta.to.shared.u64 t, %1; cvt.u32.u64 %0, t; }" : "=r"(a) : "l"(p));
    return a;
}
#define CP_ASYNC16(dst, src) \
    asm volatile("cp.async.cg.shared.global [%0], [%1], 16;" :: "r"(dst), "l"(src))
#define CP_COMMIT() asm volatile("cp.async.commit_group;" ::: "memory")
#define CP_WAIT1()  asm volatile("cp.async.wait_group 1;" ::: "memory")
#define CP_WAIT0()  asm volatile("cp.async.wait_group 0;" ::: "memory")

__device__ __forceinline__ void ldm_x4(uint32_t& r0, uint32_t& r1, uint32_t& r2, uint32_t& r3,
                                       uint32_t addr) {
    asm volatile("ldmatrix.sync.aligned.m8n8.x4.shared.b16 {%0,%1,%2,%3}, [%4];"
                 : "=r"(r0), "=r"(r1), "=r"(r2), "=r"(r3) : "r"(addr));
}
__device__ __forceinline__ void ldm_x4_t(uint32_t& r0, uint32_t& r1, uint32_t& r2, uint32_t& r3,
                                         uint32_t addr) {
    asm volatile("ldmatrix.sync.aligned.m8n8.x4.trans.shared.b16 {%0,%1,%2,%3}, [%4];"
                 : "=r"(r0), "=r"(r1), "=r"(r2), "=r"(r3) : "r"(addr));
}
__device__ __forceinline__ void mma_bf16(float c[4],
                                         uint32_t a0, uint32_t a1, uint32_t a2, uint32_t a3,
                                         uint32_t b0, uint32_t b1) {
    asm volatile("mma.sync.aligned.m16n8k16.row.col.f32.bf16.bf16.f32 "
                 "{%0,%1,%2,%3}, {%4,%5,%6,%7}, {%8,%9}, {%0,%1,%2,%3};"
                 : "+f"(c[0]), "+f"(c[1]), "+f"(c[2]), "+f"(c[3])
                 : "r"(a0), "r"(a1), "r"(a2), "r"(a3), "r"(b0), "r"(b1));
}
__device__ __forceinline__ void split2(float x, float y, uint32_t& hi, uint32_t& lo) {
    __nv_bfloat162 H, L;
    H.x = __float2bfloat16(x); H.y = __float2bfloat16(y);
    L.x = __float2bfloat16(x - __bfloat162float(H.x));
    L.y = __float2bfloat16(y - __bfloat162float(H.y));
    hi = *reinterpret_cast<uint32_t*>(&H);
    lo = *reinterpret_cast<uint32_t*>(&L);
}

// ======================================================================
// RMSNorm fused with split-bf16 emit into hi/lo planes
// ======================================================================
__global__ __launch_bounds__(256)
void rmsnorm_bf16(const float* __restrict__ x, const float* __restrict__ w,
                  __nv_bfloat16* __restrict__ yh, __nv_bfloat16* __restrict__ yl)
{
    const int row = blockIdx.x;
    const int tid = threadIdx.x;
    const float4* xr = reinterpret_cast<const float4*>(x + (size_t)row * CHD);
    float4 v0 = xr[tid];
    float4 v1 = xr[tid + 256];
    float ss = v0.x*v0.x + v0.y*v0.y + v0.z*v0.z + v0.w*v0.w
             + v1.x*v1.x + v1.y*v1.y + v1.z*v1.z + v1.w*v1.w;
#pragma unroll
    for (int o = 16; o > 0; o >>= 1) ss += __shfl_xor_sync(0xffffffffu, ss, o);
    __shared__ float red[8];
    if ((tid & 31) == 0) red[tid >> 5] = ss;
    __syncthreads();
    float tot = red[0]+red[1]+red[2]+red[3]+red[4]+red[5]+red[6]+red[7];
    const float sc = rsqrtf(tot * (1.0f / (float)CHD) + 1.1920929e-7f);

    const float4* wr = reinterpret_cast<const float4*>(w);
    __nv_bfloat16* yhr = yh + (size_t)row * CHD;
    __nv_bfloat16* ylr = yl + (size_t)row * CHD;

    float4 wv[2] = { wr[tid], wr[tid + 256] };
    float4 vv[2] = { v0, v1 };
#pragma unroll
    for (int h = 0; h < 2; h++) {
        const int k = 4 * (tid + h * 256);
        float e[4] = { vv[h].x*sc*wv[h].x, vv[h].y*sc*wv[h].y,
                       vv[h].z*sc*wv[h].z, vv[h].w*sc*wv[h].w };
        uint32_t h01, l01, h23, l23;
        split2(e[0], e[1], h01, l01);
        split2(e[2], e[3], h23, l23);
        *reinterpret_cast<uint32_t*>(yhr + k)     = h01;
        *reinterpret_cast<uint32_t*>(yhr + k + 2) = h23;
        *reinterpret_cast<uint32_t*>(ylr + k)     = l01;
        *reinterpret_cast<uint32_t*>(ylr + k + 2) = l23;
    }
}

// ======================================================================
// split-bf16 weight conversion -> hi/lo planes (row width 2048)
// ======================================================================
__global__ __launch_bounds__(256)
void convert_w(const float* __restrict__ X,
               __nv_bfloat16* __restrict__ Yh, __nv_bfloat16* __restrict__ Yl,
               int total4)
{
    const int stride = gridDim.x * blockDim.x;
    for (int i = blockIdx.x * blockDim.x + threadIdx.x; i < total4; i += stride) {
        float4 v = reinterpret_cast<const float4*>(X)[i];
        const int e0 = i * 4;
        uint32_t h01, l01, h23, l23;
        split2(v.x, v.y, h01, l01);
        split2(v.z, v.w, h23, l23);
        *reinterpret_cast<uint32_t*>(Yh + e0)     = h01;
        *reinterpret_cast<uint32_t*>(Yh + e0 + 2) = h23;
        *reinterpret_cast<uint32_t*>(Yl + e0)     = l01;
        *reinterpret_cast<uint32_t*>(Yl + e0 + 2) = l23;
    }
}

__global__ void concat_bias3(const float* __restrict__ bq, const float* __restrict__ bk,
                             const float* __restrict__ bv, float* __restrict__ bqkv)
{
    int i = threadIdx.x + blockIdx.x * blockDim.x;
    if (i < 2048) bqkv[i] = bq[i];
    else if (i < 2560) bqkv[i] = bk[i - 2048];
    else if (i < 3072) bqkv[i] = bv[i - 2560];
}

// ======================================================================
// HMMA bf16 NT GEMM, plane-based split:
//   C = Ahi*Bhi^T + Alo*Bhi^T + Ahi*Blo^T (+ bias)
// 128x256 CTA tile, BK=64 (real K=2048), 2-stage cp.async, 256 threads,
// warp tile 64x64 (2x4 warps).
// mode 0: fp32 out into Cf[*,2048].
// mode 1: QKV epilogue: n<2048 -> Q planes; else -> KV planes (col n-2048).
// ======================================================================
#define BM 128
#define BN 256
#define BK 64
#define KP 72
#define AT (128*KP)
#define BT (256*KP)
#define OFF_AH 0
#define OFF_AL AT
#define OFF_BH (2*AT)
#define OFF_BL (2*AT+BT)
#define STAGE (2*AT+2*BT)             // 55296 elems
#define NCHUNK (CHD / BK)             // 32
#define GSMEM_BYTES (2*STAGE*2)       // 221184

__global__ __launch_bounds__(256, 1)
void gemm_hmma(const __nv_bfloat16* __restrict__ Ah, const __nv_bfloat16* __restrict__ Al,
               const __nv_bfloat16* __restrict__ Bh, const __nv_bfloat16* __restrict__ Bl,
               const float* __restrict__ bias,
               float* __restrict__ Cf,
               __nv_bfloat16* __restrict__ Qhp, __nv_bfloat16* __restrict__ Qlp,
               __nv_bfloat16* __restrict__ KVhp, __nv_bfloat16* __restrict__ KVlp,
               int mode)
{
    extern __shared__ __nv_bfloat16 smem[];
    const uint32_t sb = smem_u32(smem);

    const int tid  = threadIdx.x;
    const int lane = tid & 31;
    const int wid  = tid >> 5;
    const int wm   = wid & 1;
    const int wn   = wid >> 1;
    const int m0 = blockIdx.y * BM;
    const int n0 = blockIdx.x * BN;

    const int r0 = tid >> 3;          // 0..31
    const int c0 = tid & 7;           // 16B column within 64-col tile

    auto issue = [&](int kc) {
        const int st = kc & 1;
        const uint32_t bs = sb + (uint32_t)(st * STAGE) * 2;
        const size_t ko = (size_t)kc * BK + c0 * 8;
#pragma unroll
        for (int u = 0; u < 4; u++) {
            const int r = r0 + u * 32;
            const uint32_t so = (uint32_t)((r * KP + c0 * 8) * 2);
            CP_ASYNC16(bs + OFF_AH*2 + so, Ah + (size_t)(m0 + r) * CHD + ko);
            CP_ASYNC16(bs + OFF_AL*2 + so, Al + (size_t)(m0 + r) * CHD + ko);
        }
#pragma unroll
        for (int u = 0; u < 8; u++) {
            const int r = r0 + u * 32;
            const uint32_t so = (uint32_t)((r * KP + c0 * 8) * 2);
            CP_ASYNC16(bs + OFF_BH*2 + so, Bh + (size_t)(n0 + r) * CHD + ko);
            CP_ASYNC16(bs + OFF_BL*2 + so, Bl + (size_t)(n0 + r) * CHD + ko);
        }
        CP_COMMIT();
    };

    // fragment addressing
    const int g   = lane >> 3;
    const int grw = lane & 7;
    const int aRow = wm * 64 + (g & 1) * 8 + grw;    // + i*16
    const int aCol = (g >> 1) * 8;                   // + s*16
    const int bRow = wn * 64 + (g >> 1) * 8 + grw;   // + p*16
    const int bCol = (g & 1) * 8;                    // + s*16

    float acc[4][8][4];
#pragma unroll
    for (int i = 0; i < 4; i++)
#pragma unroll
        for (int j = 0; j < 8; j++)
#pragma unroll
            for (int t = 0; t < 4; t++) acc[i][j][t] = 0.0f;

    issue(0);

    for (int kc = 0; kc < NCHUNK; kc++) {
        if (kc + 1 < NCHUNK) { issue(kc + 1); CP_WAIT1(); }
        else { CP_WAIT0(); }
        __syncthreads();

        const int st = kc & 1;
        const uint32_t bs = sb + (uint32_t)(st * STAGE) * 2;
#pragma unroll
        for (int s = 0; s < 4; s++) {
            // A fragments (hi and lo)
            uint32_t ah_[4][4], al_[4][4];
#pragma unroll
            for (int i = 0; i < 4; i++) {
                const uint32_t ao = (uint32_t)(((aRow + i * 16) * KP + aCol + s * 16) * 2);
                ldm_x4(ah_[i][0], ah_[i][1], ah_[i][2], ah_[i][3], bs + OFF_AH*2 + ao);
                ldm_x4(al_[i][0], al_[i][1], al_[i][2], al_[i][3], bs + OFF_AL*2 + ao);
            }
            // B hi fragments -> pass1 (Ahi*Bhi) + pass2 (Alo*Bhi)
            uint32_t bf[4][4];
#pragma unroll
            for (int p = 0; p < 4; p++) {
                const uint32_t bo = (uint32_t)(((bRow + p * 16) * KP + bCol + s * 16) * 2);
                ldm_x4(bf[p][0], bf[p][1], bf[p][2], bf[p][3], bs + OFF_BH*2 + bo);
            }
#pragma unroll
            for (int i = 0; i < 4; i++)
#pragma unroll
                for (int j = 0; j < 8; j++) {
                    const int p = j >> 1, q = (j & 1) * 2;
                    mma_bf16(acc[i][j], ah_[i][0], ah_[i][1], ah_[i][2], ah_[i][3],
                             bf[p][q], bf[p][q + 1]);
                    mma_bf16(acc[i][j], al_[i][0], al_[i][1], al_[i][2], al_[i][3],
                             bf[p][q], bf[p][q + 1]);
                }
            // B lo fragments -> pass3 (Ahi*Blo)
#pragma unroll
            for (int p = 0; p < 4; p++) {
                const uint32_t bo = (uint32_t)(((bRow + p * 16) * KP + bCol + s * 16) * 2);
                ldm_x4(bf[p][0], bf[p][1], bf[p][2], bf[p][3], bs + OFF_BL*2 + bo);
            }
#pragma unroll
            for (int i = 0; i < 4; i++)
#pragma unroll
                for (int j = 0; j < 8; j++) {
                    const int p = j >> 1, q = (j & 1) * 2;
                    mma_bf16(acc[i][j], ah_[i][0], ah_[i][1], ah_[i][2], ah_[i][3],
                             bf[p][q], bf[p][q + 1]);
                }
        }
        __syncthreads();
    }

    // ---- epilogue ----
    const int rowb = m0 + wm * 64 + (lane >> 2);
    const int colb = n0 + wn * 64 + 2 * (lane & 3);
#pragma unroll
    for (int j = 0; j < 8; j++) {
        const int c = colb + j * 8;
        const float b0v = bias[c], b1v = bias[c + 1];
#pragma unroll
        for (int i = 0; i < 4; i++) {
            const int r = rowb + i * 16;
            float v0 = acc[i][j][0] + b0v, v1 = acc[i][j][1] + b1v;
            float v2 = acc[i][j][2] + b0v, v3 = acc[i][j][3] + b1v;
            if (mode == 0) {
                float2 o;
                o.x = v0; o.y = v1;
                *reinterpret_cast<float2*>(Cf + (size_t)r * CHD + c) = o;
                o.x = v2; o.y = v3;
                *reinterpret_cast<float2*>(Cf + (size_t)(r + 8) * CHD + c) = o;
            } else {
                __nv_bfloat16 *Hp, *Lp;
                size_t off1, off2;
                if (c < 2048) {
                    Hp = Qhp; Lp = Qlp;
                    off1 = (size_t)r * CHD + c;
                    off2 = (size_t)(r + 8) * CHD + c;
                } else {
                    Hp = KVhp; Lp = KVlp;
                    off1 = (size_t)r * 1024 + (c - 2048);
                    off2 = (size_t)(r + 8) * 1024 + (c - 2048);
                }
                uint32_t hi, lo;
                split2(v0, v1, hi, lo);
                *reinterpret_cast<uint32_t*>(Hp + off1) = hi;
                *reinterpret_cast<uint32_t*>(Lp + off1) = lo;
                split2(v2, v3, hi, lo);
                *reinterpret_cast<uint32_t*>(Hp + off2) = hi;
                *reinterpret_cast<uint32_t*>(Lp + off2) = lo;
            }
        }
    }
}

// ======================================================================
// HMMA flash attention. BR=128, BC=64, D=128, 256 threads (8 warps),
// split-bf16 3-pass for QK^T and PV. Replacement mask (j<=i -> -1e9).
// Each block processes tiles jc >= i0; row N-1 fixed up afterwards.
// Output: hi/lo planes.
// ======================================================================
#define ABR 128
#define ABC 64
#define AST 136
#define SQH 0
#define SQL (128*AST)
#define SKV0 (2*128*AST)
#define KVPL (64*AST)
#define KVBUF (4*KVPL)
#define FA_SMEM_BYTES ((SKV0 + 2*KVBUF) * 2)   // 208896

__global__ __launch_bounds__(256)
void flash_hmma(const __nv_bfloat16* __restrict__ Qh, const __nv_bfloat16* __restrict__ Ql,
                const __nv_bfloat16* __restrict__ KVh, const __nv_bfloat16* __restrict__ KVl,
                __nv_bfloat16* __restrict__ Ahp, __nv_bfloat16* __restrict__ Alp)
{
    const int it = blockIdx.x;
    const int h  = blockIdx.y;
    const int b  = blockIdx.z;
    const int g  = h & (CKVH - 1);
    const int i0 = it * ABR;
    const int tid = threadIdx.x;
    const int lane = tid & 31;
    const int wid = tid >> 5;

    extern __shared__ __nv_bfloat16 sm[];
    const uint32_t sb = smem_u32(sm);

    {
        const size_t qbase = (size_t)(b*CN + i0) * CHD + h*CD;
#pragma unroll
        for (int u = 0; u < 8; u++) {
            const int idx = tid + u * 256;
            const int r = idx >> 4, c8 = idx & 15;
            *reinterpret_cast<uint4*>(&sm[SQH + r*AST + c8*8]) =
                *reinterpret_cast<const uint4*>(Qh + qbase + (size_t)r*CHD + c8*8);
            *reinterpret_cast<uint4*>(&sm[SQL + r*AST + c8*8]) =
                *reinterpret_cast<const uint4*>(Ql + qbase + (size_t)r*CHD + c8*8);
        }
    }

    const int jstart = i0;
    const int ntiles = (CN - jstart) / ABC;

    auto load_kv = [&](int jc, int bf) {
        const size_t kbase = (size_t)(b*CN + jc) * 1024 + g*CD;
        const size_t vbase = kbase + 512;
        const uint32_t d0 = sb + (uint32_t)(SKV0 + bf*KVBUF) * 2;
#pragma unroll
        for (int u = 0; u < 4; u++) {
            const int idx = tid + u * 256;
            const int r = idx >> 4, c8 = idx & 15;
            const uint32_t so = (uint32_t)((r*AST + c8*8) * 2);
            const size_t go = (size_t)r * 1024 + c8*8;
            CP_ASYNC16(d0 + so,              KVh + kbase + go);
            CP_ASYNC16(d0 + KVPL*2 + so,     KVl + kbase + go);
            CP_ASYNC16(d0 + 2*KVPL*2 + so,   KVh + vbase + go);
            CP_ASYNC16(d0 + 3*KVPL*2 + so,   KVl + vbase + go);
        }
        CP_COMMIT();
    };

    load_kv(jstart, 0);

    const int gmt = lane >> 3, grw = lane & 7;
    const int aRow = wid*16 + (gmt & 1)*8 + grw;
    const int aColB = (gmt >> 1) * 8;
    const int bRowB = (gmt >> 1)*8 + grw;
    const int bColB = (gmt & 1) * 8;
    const int tRow = (gmt & 1)*8 + grw;
    const int tCol = (gmt >> 1) * 8;

    const int r1 = i0 + wid*16 + (lane >> 2);
    const int r2 = r1 + 8;

    float oa[16][4];
#pragma unroll
    for (int n = 0; n < 16; n++)
#pragma unroll
        for (int t = 0; t < 4; t++) oa[n][t] = 0.0f;
    float m1 = -INFINITY, m2 = -INFINITY, l1 = 0.0f, l2 = 0.0f;

    for (int t = 0; t < ntiles; t++) {
        const int jc = jstart + t * ABC;
        const int bf = t & 1;
        if (t + 1 < ntiles) {
            load_kv(jc + ABC, (t + 1) & 1);
            CP_WAIT1();
        } else {
            CP_WAIT0();
        }
        __syncthreads();

        const uint32_t kB = sb + (uint32_t)(SKV0 + bf*KVBUF) * 2;

        float sa[8][4];
#pragma unroll
        for (int n = 0; n < 8; n++)
#pragma unroll
            for (int q = 0; q < 4; q++) sa[n][q] = 0.0f;

#pragma unroll
        for (int s = 0; s < 8; s++) {
            uint32_t qh[4], ql[4];
            ldm_x4(qh[0], qh[1], qh[2], qh[3],
                   sb + (uint32_t)((SQH + aRow*AST + aColB + s*16) * 2));
            ldm_x4(ql[0], ql[1], ql[2], ql[3],
                   sb + (uint32_t)((SQL + aRow*AST + aColB + s*16) * 2));
#pragma unroll
            for (int nt = 0; nt < 4; nt++) {
                uint32_t kh[4], kl[4];
                const uint32_t ko = (uint32_t)(((nt*16 + bRowB)*AST + bColB + s*16) * 2);
                ldm_x4(kh[0], kh[1], kh[2], kh[3], kB + ko);
                ldm_x4(kl[0], kl[1], kl[2], kl[3], kB + KVPL*2 + ko);
                mma_bf16(sa[2*nt],   qh[0], qh[1], qh[2], qh[3], kh[0], kh[1]);
                mma_bf16(sa[2*nt],   ql[0], ql[1], ql[2], ql[3], kh[0], kh[1]);
                mma_bf16(sa[2*nt],   qh[0], qh[1], qh[2], qh[3], kl[0], kl[1]);
                mma_bf16(sa[2*nt+1], qh[0], qh[1], qh[2], qh[3], kh[2], kh[3]);
                mma_bf16(sa[2*nt+1], ql[0], ql[1], ql[2], ql[3], kh[2], kh[3]);
                mma_bf16(sa[2*nt+1], qh[0], qh[1], qh[2], qh[3], kl[2], kl[3]);
            }
        }

        if (jc < i0 + ABR) {
#pragma unroll
            for (int n = 0; n < 8; n++) {
                const int c0 = jc + n*8 + (lane & 3)*2;
#pragma unroll
                for (int q = 0; q < 2; q++) {
                    if (c0 + q <= r1) sa[n][q]     = -1e9f;
                    if (c0 + q <= r2) sa[n][2 + q] = -1e9f;
                }
            }
        }

        float mx1 = -INFINITY, mx2 = -INFINITY;
#pragma unroll
        for (int n = 0; n < 8; n++) {
            mx1 = fmaxf(mx1, fmaxf(sa[n][0], sa[n][1]));
            mx2 = fmaxf(mx2, fmaxf(sa[n][2], sa[n][3]));
        }
        mx1 = fmaxf(mx1, __shfl_xor_sync(0xffffffffu, mx1, 1));
        mx1 = fmaxf(mx1, __shfl_xor_sync(0xffffffffu, mx1, 2));
        mx2 = fmaxf(mx2, __shfl_xor_sync(0xffffffffu, mx2, 1));
        mx2 = fmaxf(mx2, __shfl_xor_sync(0xffffffffu, mx2, 2));
        const float mn1 = fmaxf(m1, mx1);
        const float mn2 = fmaxf(m2, mx2);
        const float al1 = __expf(m1 - mn1);
        const float al2 = __expf(m2 - mn2);
        m1 = mn1; m2 = mn2;

        float sum1 = 0.0f, sum2 = 0.0f;
#pragma unroll
        for (int n = 0; n < 8; n++) {
            sa[n][0] = __expf(sa[n][0] - mn1); sum1 += sa[n][0];
            sa[n][1] = __expf(sa[n][1] - mn1); sum1 += sa[n][1];
            sa[n][2] = __expf(sa[n][2] - mn2); sum2 += sa[n][2];
            sa[n][3] = __expf(sa[n][3] - mn2); sum2 += sa[n][3];
        }
        sum1 += __shfl_xor_sync(0xffffffffu, sum1, 1);
        sum1 += __shfl_xor_sync(0xffffffffu, sum1, 2);
        sum2 += __shfl_xor_sync(0xffffffffu, sum2, 1);
        sum2 += __shfl_xor_sync(0xffffffffu, sum2, 2);
        l1 = l1 * al1 + sum1;
        l2 = l2 * al2 + sum2;

#pragma unroll
        for (int n = 0; n < 16; n++) {
            oa[n][0] *= al1; oa[n][1] *= al1;
            oa[n][2] *= al2; oa[n][3] *= al2;
        }

        const uint32_t vhB = kB + 2*KVPL*2;
        const uint32_t vlB = kB + 3*KVPL*2;
#pragma unroll
        for (int kt = 0; kt < 4; kt++) {
            uint32_t ph[4], pl[4];
            split2(sa[2*kt][0],   sa[2*kt][1],   ph[0], pl[0]);
            split2(sa[2*kt][2],   sa[2*kt][3],   ph[1], pl[1]);
            split2(sa[2*kt+1][0], sa[2*kt+1][1], ph[2], pl[2]);
            split2(sa[2*kt+1][2], sa[2*kt+1][3], ph[3], pl[3]);
#pragma unroll
            for (int nt = 0; nt < 8; nt++) {
                uint32_t vh[4], vl[4];
                const uint32_t vo = (uint32_t)(((kt*16 + tRow)*AST + nt*16 + tCol) * 2);
                ldm_x4_t(vh[0], vh[1], vh[2], vh[3], vhB + vo);
                ldm_x4_t(vl[0], vl[1], vl[2], vl[3], vlB + vo);
                mma_bf16(oa[2*nt],   ph[0], ph[1], ph[2], ph[3], vh[0], vh[1]);
                mma_bf16(oa[2*nt],   pl[0], pl[1], pl[2], pl[3], vh[0], vh[1]);
                mma_bf16(oa[2*nt],   ph[0], ph[1], ph[2], ph[3], vl[0], vl[1]);
                mma_bf16(oa[2*nt+1], ph[0], ph[1], ph[2], ph[3], vh[2], vh[3]);
                mma_bf16(oa[2*nt+1], pl[0], pl[1], pl[2], pl[3], vh[2], vh[3]);
                mma_bf16(oa[2*nt+1], ph[0], ph[1], ph[2], ph[3], vl[2], vl[3]);
            }
        }
        __syncthreads();
    }

    const float li1 = 1.0f / l1;
    const float li2 = 1.0f / l2;
    __nv_bfloat16* h1p = Ahp + (size_t)(b*CN + r1) * CHD;
    __nv_bfloat16* l1p = Alp + (size_t)(b*CN + r1) * CHD;
    __nv_bfloat16* h2p = Ahp + (size_t)(b*CN + r2) * CHD;
    __nv_bfloat16* l2p = Alp + (size_t)(b*CN + r2) * CHD;
#pragma unroll
    for (int n = 0; n < 16; n++) {
        const int col = h*CD + n*8 + (lane & 3)*2;
        uint32_t hi, lo;
        split2(oa[n][0] * li1, oa[n][1] * li1, hi, lo);
        *reinterpret_cast<uint32_t*>(h1p + col) = hi;
        *reinterpret_cast<uint32_t*>(l1p + col) = lo;
        split2(oa[n][2] * li2, oa[n][3] * li2, hi, lo);
        *reinterpret_cast<uint32_t*>(h2p + col) = hi;
        *reinterpret_cast<uint32_t*>(l2p + col) = lo;
    }
}

// ======================================================================
// Row N-1 fixup: fully-masked row -> uniform softmax -> mean(V).
// ======================================================================
__global__ __launch_bounds__(128)
void fix_last_row(const __nv_bfloat16* __restrict__ KVh,
                  const __nv_bfloat16* __restrict__ KVl,
                  __nv_bfloat16* __restrict__ Ahp, __nv_bfloat16* __restrict__ Alp)
{
    const int b = blockIdx.x;
    const int g = blockIdx.y;
    const int d = threadIdx.x;
    const __nv_bfloat16* vh = KVh + (size_t)(b*CN) * 1024 + 512 + g*CD + d;
    const __nv_bfloat16* vl = KVl + (size_t)(b*CN) * 1024 + 512 + g*CD + d;
    float s = 0.0f;
    for (int j = 0; j < CN; j++) {
        s += __bfloat162float(vh[(size_t)j * 1024]) + __bfloat162float(vl[(size_t)j * 1024]);
    }
    s *= (1.0f / (float)CN);
    __nv_bfloat16 hi = __float2bfloat16(s);
    __nv_bfloat16 lo = __float2bfloat16(s - __bfloat162float(hi));
    __nv_bfloat16* rh = Ahp + (size_t)(b*CN + CN - 1) * CHD;
    __nv_bfloat16* rl = Alp + (size_t)(b*CN + CN - 1) * CHD;
#pragma unroll
    for (int hh = 0; hh < 4; hh++) {
        const int h = hh * CKVH + g;
        const int col = h*CD + d;
        rh[col] = hi;
        rl[col] = lo;
    }
}

// ======================================================================
// launch
// ======================================================================
extern "C" void kernel_launch(void* const* d_in, const int* in_sizes, int n_in,
                              void* d_out, int out_size)
{
    const float* tokens = (const float*)d_in[0];
    const float* norm_w = (const float*)d_in[1];
    const float* Wq = (const float*)d_in[2];
    const float* bq = (const float*)d_in[3];
    const float* Wk = (const float*)d_in[4];
    const float* bk = (const float*)d_in[5];
    const float* Wv = (const float*)d_in[6];
    const float* bv = (const float*)d_in[7];
    const float* Wo = (const float*)d_in[8];
    const float* bo = (const float*)d_in[9];
    float* out = (float*)d_out;

    __nv_bfloat16 *xnh, *xnl, *wqkvh, *wqkvl, *woh, *wol;
    __nv_bfloat16 *qh, *ql, *kvh, *kvl, *ah, *al;
    float* bqkv;
    cudaGetSymbolAddress((void**)&xnh,   g_xnh);
    cudaGetSymbolAddress((void**)&xnl,   g_xnl);
    cudaGetSymbolAddress((void**)&wqkvh, g_wqkvh);
    cudaGetSymbolAddress((void**)&wqkvl, g_wqkvl);
    cudaGetSymbolAddress((void**)&woh,   g_woh);
    cudaGetSymbolAddress((void**)&wol,   g_wol);
    cudaGetSymbolAddress((void**)&bqkv,  g_bqkv);
    cudaGetSymbolAddress((void**)&qh,    g_qh);
    cudaGetSymbolAddress((void**)&ql,    g_ql);
    cudaGetSymbolAddress((void**)&kvh,   g_kvh);
    cudaGetSymbolAddress((void**)&kvl,   g_kvl);
    cudaGetSymbolAddress((void**)&ah,    g_ah);
    cudaGetSymbolAddress((void**)&al,    g_al);

    cudaFuncSetAttribute(gemm_hmma, cudaFuncAttributeMaxDynamicSharedMemorySize, GSMEM_BYTES);
    cudaFuncSetAttribute(flash_hmma, cudaFuncAttributeMaxDynamicSharedMemorySize, FA_SMEM_BYTES);

    // 1. RMSNorm -> hi/lo planes
    rmsnorm_bf16<<<CM, 256>>>(tokens, norm_w, xnh, xnl);

    // 2. weight conversions + bias concat
    convert_w<<<1024, 256>>>(Wq, wqkvh, wqkvl, CHD*CHD/4);
    convert_w<<<512,  256>>>(Wk, wqkvh + (size_t)2048*CHD, wqkvl + (size_t)2048*CHD, CKVD*CHD/4);
    convert_w<<<512,  256>>>(Wv, wqkvh + (size_t)2560*CHD, wqkvl + (size_t)2560*CHD, CKVD*CHD/4);
    convert_w<<<1024, 256>>>(Wo, woh, wol, CHD*CHD/4);
    concat_bias3<<<12, 256>>>(bq, bk, bv, bqkv);

    // 3. fused QKV projection -> Q / KV hi/lo planes
    gemm_hmma<<<dim3(3072/BN, CM/BM), 256, GSMEM_BYTES>>>(
        xnh, xnl, wqkvh, wqkvl, bqkv, nullptr, qh, ql, kvh, kvl, 1);

    // 4. HMMA flash attention -> a hi/lo planes, then fix row N-1
    flash_hmma<<<dim3(CN/ABR, CNH, CB), 256, FA_SMEM_BYTES>>>(qh, ql, kvh, kvl, ah, al);
    fix_last_row<<<dim3(CB, CKVH), 128>>>(kvh, kvl, ah, al);

    // 5. output projection -> d_out (fp32)
    gemm_hmma<<<dim3(CHD/BN, CM/BM), 256, GSMEM_BYTES>>>(
        ah, al, woh, wol, bo, out, nullptr, nullptr, nullptr, nullptr, 0);
}

// round 13
// speedup vs baseline: 4.4554x; 1.3188x over previous
#include <cuda_runtime.h>
#include <cuda_fp16.h>
#include <math.h>
#include <stdint.h>

// ---------------- problem constants ----------------
#define CB   2
#define CN   2048
#define CHD  2048
#define CNH  16
#define CKVH 4
#define CD   128
#define CKVD 512
#define CM   (CB*CN)     // 4096 token rows

// ---------------- scratch (device globals; no allocation allowed) ----------------
__device__ __half g_xnh[CM*CHD];     // normed tokens hi plane (fp16)
__device__ __half g_xnl[CM*CHD];     // normed tokens lo plane
__device__ __half g_wqkvh[3072*CHD]; // [Wq; Wk; Wv] hi only
__device__ __half g_woh[CHD*CHD];    // Wo hi only
__device__ float  g_bqkv[3072];
__device__ __half g_qh[CM*CHD];      // Q hi
__device__ __half g_ql[CM*CHD];      // Q lo
__device__ __half g_kvh[CM*1024];    // [K | V] hi
__device__ __half g_kvl[CM*1024];    // [K | V] lo (K-lo used by flash; V-lo by fixup)
__device__ __half g_ah[CM*CHD];      // attention out hi
__device__ __half g_al[CM*CHD];      // attention out lo

// ======================================================================
// helpers
// ======================================================================
__device__ __forceinline__ uint32_t smem_u32(const void* p) {
    uint32_t a;
    asm("{ .reg .u64 t; cvta.to.shared.u64 t, %1; cvt.u32.u64 %0, t; }" : "=r"(a) : "l"(p));
    return a;
}
#define CP_ASYNC16(dst, src) \
    asm volatile("cp.async.cg.shared.global [%0], [%1], 16;" :: "r"(dst), "l"(src))
#define CP_COMMIT() asm volatile("cp.async.commit_group;" ::: "memory")
#define CP_WAIT2()  asm volatile("cp.async.wait_group 2;" ::: "memory")
#define CP_WAIT1()  asm volatile("cp.async.wait_group 1;" ::: "memory")
#define CP_WAIT0()  asm volatile("cp.async.wait_group 0;" ::: "memory")

__device__ __forceinline__ void ldm_x4(uint32_t& r0, uint32_t& r1, uint32_t& r2, uint32_t& r3,
                                       uint32_t addr) {
    asm volatile("ldmatrix.sync.aligned.m8n8.x4.shared.b16 {%0,%1,%2,%3}, [%4];"
                 : "=r"(r0), "=r"(r1), "=r"(r2), "=r"(r3) : "r"(addr));
}
__device__ __forceinline__ void ldm_x4_t(uint32_t& r0, uint32_t& r1, uint32_t& r2, uint32_t& r3,
                                         uint32_t addr) {
    asm volatile("ldmatrix.sync.aligned.m8n8.x4.trans.shared.b16 {%0,%1,%2,%3}, [%4];"
                 : "=r"(r0), "=r"(r1), "=r"(r2), "=r"(r3) : "r"(addr));
}
// fp16 MMA, fp32 accumulate
__device__ __forceinline__ void mma_f16(float c[4],
                                        uint32_t a0, uint32_t a1, uint32_t a2, uint32_t a3,
                                        uint32_t b0, uint32_t b1) {
    asm volatile("mma.sync.aligned.m16n8k16.row.col.f32.f16.f16.f32 "
                 "{%0,%1,%2,%3}, {%4,%5,%6,%7}, {%8,%9}, {%0,%1,%2,%3};"
                 : "+f"(c[0]), "+f"(c[1]), "+f"(c[2]), "+f"(c[3])
                 : "r"(a0), "r"(a1), "r"(a2), "r"(a3), "r"(b0), "r"(b1));
}
// split float pair into packed fp16 hi pair + lo pair
__device__ __forceinline__ void split2h(float x, float y, uint32_t& hi, uint32_t& lo) {
    __half2 H, L;
    H.x = __float2half(x); H.y = __float2half(y);
    L.x = __float2half(x - __half2float(H.x));
    L.y = __float2half(y - __half2float(H.y));
    hi = *reinterpret_cast<uint32_t*>(&H);
    lo = *reinterpret_cast<uint32_t*>(&L);
}
__device__ __forceinline__ uint32_t pack_h2(float x, float y) {
    __half2 H;
    H.x = __float2half(x); H.y = __float2half(y);
    return *reinterpret_cast<uint32_t*>(&H);
}

// ======================================================================
// RMSNorm fused with fp16 split emit into hi/lo planes
// ======================================================================
__global__ __launch_bounds__(256)
void rmsnorm_f16(const float* __restrict__ x, const float* __restrict__ w,
                 __half* __restrict__ yh, __half* __restrict__ yl)
{
    const int row = blockIdx.x;
    const int tid = threadIdx.x;
    const float4* xr = reinterpret_cast<const float4*>(x + (size_t)row * CHD);
    float4 v0 = xr[tid];
    float4 v1 = xr[tid + 256];
    float ss = v0.x*v0.x + v0.y*v0.y + v0.z*v0.z + v0.w*v0.w
             + v1.x*v1.x + v1.y*v1.y + v1.z*v1.z + v1.w*v1.w;
#pragma unroll
    for (int o = 16; o > 0; o >>= 1) ss += __shfl_xor_sync(0xffffffffu, ss, o);
    __shared__ float red[8];
    if ((tid & 31) == 0) red[tid >> 5] = ss;
    __syncthreads();
    float tot = red[0]+red[1]+red[2]+red[3]+red[4]+red[5]+red[6]+red[7];
    const float sc = rsqrtf(tot * (1.0f / (float)CHD) + 1.1920929e-7f);

    const float4* wr = reinterpret_cast<const float4*>(w);
    __half* yhr = yh + (size_t)row * CHD;
    __half* ylr = yl + (size_t)row * CHD;

    float4 wv[2] = { wr[tid], wr[tid + 256] };
    float4 vv[2] = { v0, v1 };
#pragma unroll
    for (int h = 0; h < 2; h++) {
        const int k = 4 * (tid + h * 256);
        float e[4] = { vv[h].x*sc*wv[h].x, vv[h].y*sc*wv[h].y,
                       vv[h].z*sc*wv[h].z, vv[h].w*sc*wv[h].w };
        uint32_t h01, l01, h23, l23;
        split2h(e[0], e[1], h01, l01);
        split2h(e[2], e[3], h23, l23);
        *reinterpret_cast<uint32_t*>(yhr + k)     = h01;
        *reinterpret_cast<uint32_t*>(yhr + k + 2) = h23;
        *reinterpret_cast<uint32_t*>(ylr + k)     = l01;
        *reinterpret_cast<uint32_t*>(ylr + k + 2) = l23;
    }
}

// ======================================================================
// weight conversion -> fp16 hi plane only
// ======================================================================
__global__ __launch_bounds__(256)
void convert_w(const float* __restrict__ X, __half* __restrict__ Yh, int total4)
{
    const int stride = gridDim.x * blockDim.x;
    for (int i = blockIdx.x * blockDim.x + threadIdx.x; i < total4; i += stride) {
        float4 v = reinterpret_cast<const float4*>(X)[i];
        const int e0 = i * 4;
        *reinterpret_cast<uint32_t*>(Yh + e0)     = pack_h2(v.x, v.y);
        *reinterpret_cast<uint32_t*>(Yh + e0 + 2) = pack_h2(v.z, v.w);
    }
}

__global__ void concat_bias3(const float* __restrict__ bq, const float* __restrict__ bk,
                             const float* __restrict__ bv, float* __restrict__ bqkv)
{
    int i = threadIdx.x + blockIdx.x * blockDim.x;
    if (i < 2048) bqkv[i] = bq[i];
    else if (i < 2560) bqkv[i] = bk[i - 2048];
    else if (i < 3072) bqkv[i] = bv[i - 2560];
}

// ======================================================================
// HMMA fp16 NT GEMM, 2-pass plane split:
//   C = Ahi*Bhi^T + Alo*Bhi^T (+ bias)     (weight residual dropped)
// 128x256 CTA tile, BK=64, 3-stage cp.async, 256 threads, warp tile 64x64.
// mode 0: fp32 out into Cf[*,2048].
// mode 1: QKV epilogue: n<2048 -> Q planes; else -> KV planes (col n-2048).
// ======================================================================
#define BM 128
#define BN 256
#define BK 64
#define KP 72
#define AT (128*KP)                   // 9216 elems
#define BT (256*KP)                   // 18432 elems
#define OFF_AH 0
#define OFF_AL AT
#define OFF_BH (2*AT)
#define STAGE (2*AT+BT)               // 36864 elems = 73728 B
#define NCHUNK (CHD / BK)             // 32
#define GSMEM_BYTES (3*STAGE*2)       // 221184

__global__ __launch_bounds__(256, 1)
void gemm_hmma(const __half* __restrict__ Ah, const __half* __restrict__ Al,
               const __half* __restrict__ Bh,
               const float* __restrict__ bias,
               float* __restrict__ Cf,
               __half* __restrict__ Qhp, __half* __restrict__ Qlp,
               __half* __restrict__ KVhp, __half* __restrict__ KVlp,
               int mode)
{
    extern __shared__ __half smem[];
    const uint32_t sb = smem_u32(smem);

    const int tid  = threadIdx.x;
    const int lane = tid & 31;
    const int wid  = tid >> 5;
    const int wm   = wid & 1;
    const int wn   = wid >> 1;
    const int m0 = blockIdx.y * BM;
    const int n0 = blockIdx.x * BN;

    const int r0 = tid >> 3;          // 0..31
    const int c0 = tid & 7;           // 16B column within 64-col k-chunk

    auto issue = [&](int kc) {
        const int st = kc % 3;
        const uint32_t bs = sb + (uint32_t)(st * STAGE) * 2;
        const size_t ko = (size_t)kc * BK + c0 * 8;
#pragma unroll
        for (int u = 0; u < 4; u++) {
            const int r = r0 + u * 32;
            const uint32_t so = (uint32_t)((r * KP + c0 * 8) * 2);
            CP_ASYNC16(bs + OFF_AH*2 + so, Ah + (size_t)(m0 + r) * CHD + ko);
            CP_ASYNC16(bs + OFF_AL*2 + so, Al + (size_t)(m0 + r) * CHD + ko);
        }
#pragma unroll
        for (int u = 0; u < 8; u++) {
            const int r = r0 + u * 32;
            const uint32_t so = (uint32_t)((r * KP + c0 * 8) * 2);
            CP_ASYNC16(bs + OFF_BH*2 + so, Bh + (size_t)(n0 + r) * CHD + ko);
        }
        CP_COMMIT();
    };

    // fragment addressing
    const int g   = lane >> 3;
    const int grw = lane & 7;
    const int aRow = wm * 64 + (g & 1) * 8 + grw;    // + i*16
    const int aCol = (g >> 1) * 8;                   // + s*16
    const int bRow = wn * 64 + (g >> 1) * 8 + grw;   // + p*16
    const int bCol = (g & 1) * 8;                    // + s*16

    float acc[4][8][4];
#pragma unroll
    for (int i = 0; i < 4; i++)
#pragma unroll
        for (int j = 0; j < 8; j++)
#pragma unroll
            for (int t = 0; t < 4; t++) acc[i][j][t] = 0.0f;

    issue(0);
    issue(1);

    for (int kc = 0; kc < NCHUNK; kc++) {
        if (kc + 2 < NCHUNK) { issue(kc + 2); CP_WAIT2(); }
        else if (kc + 1 < NCHUNK) { CP_WAIT1(); }
        else { CP_WAIT0(); }
        __syncthreads();

        const int st = kc % 3;
        const uint32_t bs = sb + (uint32_t)(st * STAGE) * 2;
#pragma unroll
        for (int s = 0; s < 4; s++) {
            uint32_t ah_[4][4], al_[4][4];
#pragma unroll
            for (int i = 0; i < 4; i++) {
                const uint32_t ao = (uint32_t)(((aRow + i * 16) * KP + aCol + s * 16) * 2);
                ldm_x4(ah_[i][0], ah_[i][1], ah_[i][2], ah_[i][3], bs + OFF_AH*2 + ao);
                ldm_x4(al_[i][0], al_[i][1], al_[i][2], al_[i][3], bs + OFF_AL*2 + ao);
            }
            uint32_t bf[4][4];
#pragma unroll
            for (int p = 0; p < 4; p++) {
                const uint32_t bo = (uint32_t)(((bRow + p * 16) * KP + bCol + s * 16) * 2);
                ldm_x4(bf[p][0], bf[p][1], bf[p][2], bf[p][3], bs + OFF_BH*2 + bo);
            }
#pragma unroll
            for (int i = 0; i < 4; i++)
#pragma unroll
                for (int j = 0; j < 8; j++) {
                    const int p = j >> 1, q = (j & 1) * 2;
                    mma_f16(acc[i][j], ah_[i][0], ah_[i][1], ah_[i][2], ah_[i][3],
                            bf[p][q], bf[p][q + 1]);
                    mma_f16(acc[i][j], al_[i][0], al_[i][1], al_[i][2], al_[i][3],
                            bf[p][q], bf[p][q + 1]);
                }
        }
        __syncthreads();
    }

    // ---- epilogue ----
    const int rowb = m0 + wm * 64 + (lane >> 2);
    const int colb = n0 + wn * 64 + 2 * (lane & 3);
#pragma unroll
    for (int j = 0; j < 8; j++) {
        const int c = colb + j * 8;
        const float b0v = bias[c], b1v = bias[c + 1];
#pragma unroll
        for (int i = 0; i < 4; i++) {
            const int r = rowb + i * 16;
            float v0 = acc[i][j][0] + b0v, v1 = acc[i][j][1] + b1v;
            float v2 = acc[i][j][2] + b0v, v3 = acc[i][j][3] + b1v;
            if (mode == 0) {
                float2 o;
                o.x = v0; o.y = v1;
                *reinterpret_cast<float2*>(Cf + (size_t)r * CHD + c) = o;
                o.x = v2; o.y = v3;
                *reinterpret_cast<float2*>(Cf + (size_t)(r + 8) * CHD + c) = o;
            } else {
                __half *Hp, *Lp;
                size_t off1, off2;
                if (c < 2048) {
                    Hp = Qhp; Lp = Qlp;
                    off1 = (size_t)r * CHD + c;
                    off2 = (size_t)(r + 8) * CHD + c;
                } else {
                    Hp = KVhp; Lp = KVlp;
                    off1 = (size_t)r * 1024 + (c - 2048);
                    off2 = (size_t)(r + 8) * 1024 + (c - 2048);
                }
                uint32_t hi, lo;
                split2h(v0, v1, hi, lo);
                *reinterpret_cast<uint32_t*>(Hp + off1) = hi;
                *reinterpret_cast<uint32_t*>(Lp + off1) = lo;
                split2h(v2, v3, hi, lo);
                *reinterpret_cast<uint32_t*>(Hp + off2) = hi;
                *reinterpret_cast<uint32_t*>(Lp + off2) = lo;
            }
        }
    }
}

// ======================================================================
// HMMA flash attention, fp16 planes. BR=128, BC=64, D=128, 256 threads.
// QK^T: 3-pass (qh*kh + ql*kh + qh*kl). PV: 2-pass (ph*vh + pl*vh; V lo
// dropped, err ~eps_fp16). Replacement mask (j<=i -> -1e9), no scaling.
// KV smem buffer holds 3 planes: kh, kl, vh.
// ======================================================================
#define ABR 128
#define ABC 64
#define AST 136
#define SQH 0
#define SQL (128*AST)
#define SKV0 (2*128*AST)
#define KVPL (64*AST)
#define KVBUF (3*KVPL)
#define FA_SMEM_BYTES ((SKV0 + 2*KVBUF) * 2)   // 174080

__global__ __launch_bounds__(256)
void flash_hmma(const __half* __restrict__ Qh, const __half* __restrict__ Ql,
                const __half* __restrict__ KVh, const __half* __restrict__ KVl,
                __half* __restrict__ Ahp, __half* __restrict__ Alp)
{
    const int it = blockIdx.x;
    const int h  = blockIdx.y;
    const int b  = blockIdx.z;
    const int g  = h & (CKVH - 1);
    const int i0 = it * ABR;
    const int tid = threadIdx.x;
    const int lane = tid & 31;
    const int wid = tid >> 5;

    extern __shared__ __half sm[];
    const uint32_t sb = smem_u32(sm);

    {
        const size_t qbase = (size_t)(b*CN + i0) * CHD + h*CD;
#pragma unroll
        for (int u = 0; u < 8; u++) {
            const int idx = tid + u * 256;
            const int r = idx >> 4, c8 = idx & 15;
            *reinterpret_cast<uint4*>(&sm[SQH + r*AST + c8*8]) =
                *reinterpret_cast<const uint4*>(Qh + qbase + (size_t)r*CHD + c8*8);
            *reinterpret_cast<uint4*>(&sm[SQL + r*AST + c8*8]) =
                *reinterpret_cast<const uint4*>(Ql + qbase + (size_t)r*CHD + c8*8);
        }
    }

    const int jstart = i0;
    const int ntiles = (CN - jstart) / ABC;

    auto load_kv = [&](int jc, int bf) {
        const size_t kbase = (size_t)(b*CN + jc) * 1024 + g*CD;
        const size_t vbase = kbase + 512;
        const uint32_t d0 = sb + (uint32_t)(SKV0 + bf*KVBUF) * 2;
#pragma unroll
        for (int u = 0; u < 4; u++) {
            const int idx = tid + u * 256;
            const int r = idx >> 4, c8 = idx & 15;
            const uint32_t so = (uint32_t)((r*AST + c8*8) * 2);
            const size_t go = (size_t)r * 1024 + c8*8;
            CP_ASYNC16(d0 + so,              KVh + kbase + go);   // kh
            CP_ASYNC16(d0 + KVPL*2 + so,     KVl + kbase + go);   // kl
            CP_ASYNC16(d0 + 2*KVPL*2 + so,   KVh + vbase + go);   // vh
        }
        CP_COMMIT();
    };

    load_kv(jstart, 0);

    const int gmt = lane >> 3, grw = lane & 7;
    const int aRow = wid*16 + (gmt & 1)*8 + grw;
    const int aColB = (gmt >> 1) * 8;
    const int bRowB = (gmt >> 1)*8 + grw;
    const int bColB = (gmt & 1) * 8;
    const int tRow = (gmt & 1)*8 + grw;
    const int tCol = (gmt >> 1) * 8;

    const int r1 = i0 + wid*16 + (lane >> 2);
    const int r2 = r1 + 8;

    float oa[16][4];
#pragma unroll
    for (int n = 0; n < 16; n++)
#pragma unroll
        for (int t = 0; t < 4; t++) oa[n][t] = 0.0f;
    float m1 = -INFINITY, m2 = -INFINITY, l1 = 0.0f, l2 = 0.0f;

    for (int t = 0; t < ntiles; t++) {
        const int jc = jstart + t * ABC;
        const int bf = t & 1;
        if (t + 1 < ntiles) {
            load_kv(jc + ABC, (t + 1) & 1);
            CP_WAIT1();
        } else {
            CP_WAIT0();
        }
        __syncthreads();

        const uint32_t kB = sb + (uint32_t)(SKV0 + bf*KVBUF) * 2;

        float sa[8][4];
#pragma unroll
        for (int n = 0; n < 8; n++)
#pragma unroll
            for (int q = 0; q < 4; q++) sa[n][q] = 0.0f;

#pragma unroll
        for (int s = 0; s < 8; s++) {
            uint32_t qh[4], ql[4];
            ldm_x4(qh[0], qh[1], qh[2], qh[3],
                   sb + (uint32_t)((SQH + aRow*AST + aColB + s*16) * 2));
            ldm_x4(ql[0], ql[1], ql[2], ql[3],
                   sb + (uint32_t)((SQL + aRow*AST + aColB + s*16) * 2));
#pragma unroll
            for (int nt = 0; nt < 4; nt++) {
                uint32_t kh[4], kl[4];
                const uint32_t ko = (uint32_t)(((nt*16 + bRowB)*AST + bColB + s*16) * 2);
                ldm_x4(kh[0], kh[1], kh[2], kh[3], kB + ko);
                ldm_x4(kl[0], kl[1], kl[2], kl[3], kB + KVPL*2 + ko);
                mma_f16(sa[2*nt],   qh[0], qh[1], qh[2], qh[3], kh[0], kh[1]);
                mma_f16(sa[2*nt],   ql[0], ql[1], ql[2], ql[3], kh[0], kh[1]);
                mma_f16(sa[2*nt],   qh[0], qh[1], qh[2], qh[3], kl[0], kl[1]);
                mma_f16(sa[2*nt+1], qh[0], qh[1], qh[2], qh[3], kh[2], kh[3]);
                mma_f16(sa[2*nt+1], ql[0], ql[1], ql[2], ql[3], kh[2], kh[3]);
                mma_f16(sa[2*nt+1], qh[0], qh[1], qh[2], qh[3], kl[2], kl[3]);
            }
        }

        if (jc < i0 + ABR) {
#pragma unroll
            for (int n = 0; n < 8; n++) {
                const int c0 = jc + n*8 + (lane & 3)*2;
#pragma unroll
                for (int q = 0; q < 2; q++) {
                    if (c0 + q <= r1) sa[n][q]     = -1e9f;
                    if (c0 + q <= r2) sa[n][2 + q] = -1e9f;
                }
            }
        }

        float mx1 = -INFINITY, mx2 = -INFINITY;
#pragma unroll
        for (int n = 0; n < 8; n++) {
            mx1 = fmaxf(mx1, fmaxf(sa[n][0], sa[n][1]));
            mx2 = fmaxf(mx2, fmaxf(sa[n][2], sa[n][3]));
        }
        mx1 = fmaxf(mx1, __shfl_xor_sync(0xffffffffu, mx1, 1));
        mx1 = fmaxf(mx1, __shfl_xor_sync(0xffffffffu, mx1, 2));
        mx2 = fmaxf(mx2, __shfl_xor_sync(0xffffffffu, mx2, 1));
        mx2 = fmaxf(mx2, __shfl_xor_sync(0xffffffffu, mx2, 2));
        const float mn1 = fmaxf(m1, mx1);
        const float mn2 = fmaxf(m2, mx2);
        const float al1 = __expf(m1 - mn1);
        const float al2 = __expf(m2 - mn2);
        m1 = mn1; m2 = mn2;

        float sum1 = 0.0f, sum2 = 0.0f;
#pragma unroll
        for (int n = 0; n < 8; n++) {
            sa[n][0] = __expf(sa[n][0] - mn1); sum1 += sa[n][0];
            sa[n][1] = __expf(sa[n][1] - mn1); sum1 += sa[n][1];
            sa[n][2] = __expf(sa[n][2] - mn2); sum2 += sa[n][2];
            sa[n][3] = __expf(sa[n][3] - mn2); sum2 += sa[n][3];
        }
        sum1 += __shfl_xor_sync(0xffffffffu, sum1, 1);
        sum1 += __shfl_xor_sync(0xffffffffu, sum1, 2);
        sum2 += __shfl_xor_sync(0xffffffffu, sum2, 1);
        sum2 += __shfl_xor_sync(0xffffffffu, sum2, 2);
        l1 = l1 * al1 + sum1;
        l2 = l2 * al2 + sum2;

#pragma unroll
        for (int n = 0; n < 16; n++) {
            oa[n][0] *= al1; oa[n][1] *= al1;
            oa[n][2] *= al2; oa[n][3] *= al2;
        }

        const uint32_t vhB = kB + 2*KVPL*2;
#pragma unroll
        for (int kt = 0; kt < 4; kt++) {
            uint32_t ph[4], pl[4];
            split2h(sa[2*kt][0],   sa[2*kt][1],   ph[0], pl[0]);
            split2h(sa[2*kt][2],   sa[2*kt][3],   ph[1], pl[1]);
            split2h(sa[2*kt+1][0], sa[2*kt+1][1], ph[2], pl[2]);
            split2h(sa[2*kt+1][2], sa[2*kt+1][3], ph[3], pl[3]);
#pragma unroll
            for (int nt = 0; nt < 8; nt++) {
                uint32_t vh[4];
                const uint32_t vo = (uint32_t)(((kt*16 + tRow)*AST + nt*16 + tCol) * 2);
                ldm_x4_t(vh[0], vh[1], vh[2], vh[3], vhB + vo);
                mma_f16(oa[2*nt],   ph[0], ph[1], ph[2], ph[3], vh[0], vh[1]);
                mma_f16(oa[2*nt],   pl[0], pl[1], pl[2], pl[3], vh[0], vh[1]);
                mma_f16(oa[2*nt+1], ph[0], ph[1], ph[2], ph[3], vh[2], vh[3]);
                mma_f16(oa[2*nt+1], pl[0], pl[1], pl[2], pl[3], vh[2], vh[3]);
            }
        }
        __syncthreads();
    }

    const float li1 = 1.0f / l1;
    const float li2 = 1.0f / l2;
    __half* h1p = Ahp + (size_t)(b*CN + r1) * CHD;
    __half* l1p = Alp + (size_t)(b*CN + r1) * CHD;
    __half* h2p = Ahp + (size_t)(b*CN + r2) * CHD;
    __half* l2p = Alp + (size_t)(b*CN + r2) * CHD;
#pragma unroll
    for (int n = 0; n < 16; n++) {
        const int col = h*CD + n*8 + (lane & 3)*2;
        uint32_t hi, lo;
        split2h(oa[n][0] * li1, oa[n][1] * li1, hi, lo);
        *reinterpret_cast<uint32_t*>(h1p + col) = hi;
        *reinterpret_cast<uint32_t*>(l1p + col) = lo;
        split2h(oa[n][2] * li2, oa[n][3] * li2, hi, lo);
        *reinterpret_cast<uint32_t*>(h2p + col) = hi;
        *reinterpret_cast<uint32_t*>(l2p + col) = lo;
    }
}

// ======================================================================
// Row N-1 fixup: fully-masked row -> uniform softmax -> mean(V).
// 512 threads: 4-way parallel over j per d.
// ======================================================================
__global__ __launch_bounds__(512)
void fix_last_row(const __half* __restrict__ KVh,
                  const __half* __restrict__ KVl,
                  __half* __restrict__ Ahp, __half* __restrict__ Alp)
{
    const int b = blockIdx.x;
    const int g = blockIdx.y;
    const int d = threadIdx.x & 127;
    const int part = threadIdx.x >> 7;       // 0..3
    __shared__ float acc[4][128];

    const __half* vh = KVh + (size_t)(b*CN) * 1024 + 512 + g*CD + d;
    const __half* vl = KVl + (size_t)(b*CN) * 1024 + 512 + g*CD + d;
    float s = 0.0f;
    for (int j = part * 512; j < (part + 1) * 512; j++) {
        s += __half2float(vh[(size_t)j * 1024]) + __half2float(vl[(size_t)j * 1024]);
    }
    acc[part][d] = s;
    __syncthreads();
    if (part == 0) {
        float tot = (acc[0][d] + acc[1][d] + acc[2][d] + acc[3][d]) * (1.0f / (float)CN);
        __half hi = __float2half(tot);
        __half lo = __float2half(tot - __half2float(hi));
        __half* rh = Ahp + (size_t)(b*CN + CN - 1) * CHD;
        __half* rl = Alp + (size_t)(b*CN + CN - 1) * CHD;
#pragma unroll
        for (int hh = 0; hh < 4; hh++) {
            const int h = hh * CKVH + g;
            const int col = h*CD + d;
            rh[col] = hi;
            rl[col] = lo;
        }
    }
}

// ======================================================================
// launch
// ======================================================================
extern "C" void kernel_launch(void* const* d_in, const int* in_sizes, int n_in,
                              void* d_out, int out_size)
{
    const float* tokens = (const float*)d_in[0];
    const float* norm_w = (const float*)d_in[1];
    const float* Wq = (const float*)d_in[2];
    const float* bq = (const float*)d_in[3];
    const float* Wk = (const float*)d_in[4];
    const float* bk = (const float*)d_in[5];
    const float* Wv = (const float*)d_in[6];
    const float* bv = (const float*)d_in[7];
    const float* Wo = (const float*)d_in[8];
    const float* bo = (const float*)d_in[9];
    float* out = (float*)d_out;

    __half *xnh, *xnl, *wqkvh, *woh, *qh, *ql, *kvh, *kvl, *ah, *al;
    float* bqkv;
    cudaGetSymbolAddress((void**)&xnh,   g_xnh);
    cudaGetSymbolAddress((void**)&xnl,   g_xnl);
    cudaGetSymbolAddress((void**)&wqkvh, g_wqkvh);
    cudaGetSymbolAddress((void**)&woh,   g_woh);
    cudaGetSymbolAddress((void**)&bqkv,  g_bqkv);
    cudaGetSymbolAddress((void**)&qh,    g_qh);
    cudaGetSymbolAddress((void**)&ql,    g_ql);
    cudaGetSymbolAddress((void**)&kvh,   g_kvh);
    cudaGetSymbolAddress((void**)&kvl,   g_kvl);
    cudaGetSymbolAddress((void**)&ah,    g_ah);
    cudaGetSymbolAddress((void**)&al,    g_al);

    cudaFuncSetAttribute(gemm_hmma, cudaFuncAttributeMaxDynamicSharedMemorySize, GSMEM_BYTES);
    cudaFuncSetAttribute(flash_hmma, cudaFuncAttributeMaxDynamicSharedMemorySize, FA_SMEM_BYTES);

    // 1. RMSNorm -> fp16 hi/lo planes
    rmsnorm_f16<<<CM, 256>>>(tokens, norm_w, xnh, xnl);

    // 2. weight conversions (hi only) + bias concat
    convert_w<<<1024, 256>>>(Wq, wqkvh, CHD*CHD/4);
    convert_w<<<512,  256>>>(Wk, wqkvh + (size_t)2048*CHD, CKVD*CHD/4);
    convert_w<<<512,  256>>>(Wv, wqkvh + (size_t)2560*CHD, CKVD*CHD/4);
    convert_w<<<1024, 256>>>(Wo, woh, CHD*CHD/4);
    concat_bias3<<<12, 256>>>(bq, bk, bv, bqkv);

    // 3. fused QKV projection -> Q / KV hi/lo planes
    gemm_hmma<<<dim3(3072/BN, CM/BM), 256, GSMEM_BYTES>>>(
        xnh, xnl, wqkvh, bqkv, nullptr, qh, ql, kvh, kvl, 1);

    // 4. flash attention -> a hi/lo planes, then fix row N-1
    flash_hmma<<<dim3(CN/ABR, CNH, CB), 256, FA_SMEM_BYTES>>>(qh, ql, kvh, kvl, ah, al);
    fix_last_row<<<dim3(CB, CKVH), 512>>>(kvh, kvl, ah, al);

    // 5. output projection -> d_out (fp32)
    gemm_hmma<<<dim3(CHD/BN, CM/BM), 256, GSMEM_BYTES>>>(
        ah, al, woh, bo, out, nullptr, nullptr, nullptr, nullptr, 0);
}